// round 9
// baseline (speedup 1.0000x reference)
#include <cuda_runtime.h>
#include <math.h>

#define DEV_INLINE __device__ __forceinline__

constexpr float EPSF = 1e-6f;

// packed projection column offsets
constexpr int OFF_WV = 0;
constexpr int OFF_EV = 64;
constexpr int OFF_FG = 128;
constexpr int OFF_AG = 132;
constexpr int OFF_WG = 133;
constexpr int OFF_RM = 134;
constexpr int OFF_WS = 146;
constexpr int OFF_RS = 147;
constexpr int OFF_WK = 151;
constexpr int OFF_RK = 215;

// output offsets (floats): read_words, memory, read_weights, write_weights,
// link, precedence, usage
constexpr long O_RW    = 0L;
constexpr long O_MEM   = 262144L;
constexpr long O_RWT   = 17039360L;
constexpr long O_WW    = 18087936L;
constexpr long O_LINK  = 18350080L;
constexpr long O_PREC  = 85458944L;
constexpr long O_USAGE = 85721088L;

__device__ float g_WP[1024 * 512];
__device__ float g_bias[512];
__device__ float g_P[1024 * 512];
__device__ float g_ww[1024 * 256];
__device__ float g_mn2[1024 * 256];
__device__ float g_rdot[1024 * 4 * 256];
__device__ float g_rkn[1024 * 4];
__device__ float g_fwd[1024 * 4 * 256];          // forward weights [b][r][n]
__device__ float g_bpart[1024 * 4 * 4 * 256];    // backward partials [b][q][r][n]

__constant__ int c_start[11] = {0, 64, 128, 132, 133, 134, 146, 147, 151, 215, 471};

struct WPtrs { const float* W[10]; const float* b[10]; };

DEV_INLINE float sigmoidf_(float x) { return 1.0f / (1.0f + expf(-x)); }
DEV_INLINE float softplusf_(float x) { return x > 20.0f ? x : log1pf(expf(x)); }

DEV_INLINE float warpSum(float v) {
#pragma unroll
    for (int o = 16; o > 0; o >>= 1) v += __shfl_xor_sync(0xffffffffu, v, o);
    return v;
}

DEV_INLINE float halfSum(float v) {
#pragma unroll
    for (int o = 8; o > 0; o >>= 1) v += __shfl_xor_sync(0xffffffffu, v, o);
    return v;
}

DEV_INLINE float blockSumFast(float v, float* s8) {
    __syncthreads();
    v = warpSum(v);
    if ((threadIdx.x & 31) == 0) s8[threadIdx.x >> 5] = v;
    __syncthreads();
    float r = 0.f;
#pragma unroll
    for (int k = 0; k < 8; k++) r += s8[k];
    return r;
}

DEV_INLINE float blockMaxFast(float v, float* s8) {
    __syncthreads();
#pragma unroll
    for (int o = 16; o > 0; o >>= 1) v = fmaxf(v, __shfl_xor_sync(0xffffffffu, v, o));
    if ((threadIdx.x & 31) == 0) s8[threadIdx.x >> 5] = v;
    __syncthreads();
    float r = s8[0];
#pragma unroll
    for (int k = 1; k < 8; k++) r = fmaxf(r, s8[k]);
    return r;
}

// ---------------------------------------------------------------------------
// K0: pack 10 weight matrices into [1024][512] (cols >= 471 zero) + bias row
// ---------------------------------------------------------------------------
__global__ void k_pack(WPtrs p) {
    int idx = blockIdx.x * blockDim.x + threadIdx.x;
    int k = idx >> 9;
    int c = idx & 511;
    float v = 0.f, bv = 0.f;
    if (c < 471) {
        int s = 0;
#pragma unroll
        for (int i = 1; i < 10; i++) if (c >= c_start[i]) s = i;
        int lc = c - c_start[s];
        int od = c_start[s + 1] - c_start[s];
        v = p.W[s][k * od + lc];
        bv = p.b[s][lc];
    }
    g_WP[idx] = v;
    if (k == 0) g_bias[c] = bv;
}

// ---------------------------------------------------------------------------
// K1: P[1024][512] = controller @ WP + bias.  32x64 tile, BK=16, 256 thr,
//     grid (8, 32) = 256 blocks -> full SM coverage + 2 CTAs/SM.
// ---------------------------------------------------------------------------
__global__ __launch_bounds__(256) void k_gemm(const float* __restrict__ A) {
    __shared__ __align__(16) float sA[16][32];
    __shared__ __align__(16) float sB[16][64];
    int t = threadIdx.x;
    int bx = blockIdx.x, by = blockIdx.y;
    int tx = t & 15, ty = t >> 4;
    int arow = t >> 3, ak = (t & 7) << 1;      // A: 32 rows x 16 k, float2 per thread
    int brow = t >> 4, bcol = (t & 15) << 2;   // B: 16 k x 64 cols, float4 per thread

    const float* aptr = A + (long)(by * 32 + arow) * 1024 + ak;
    const float* bptr = g_WP + (long)brow * 512 + bx * 64 + bcol;

    float acc[2][4];
#pragma unroll
    for (int i = 0; i < 2; i++)
#pragma unroll
        for (int j = 0; j < 4; j++) acc[i][j] = 0.f;

    float2 av = *(const float2*)(aptr);
    float4 bv = *(const float4*)(bptr);

    for (int kk = 0; kk < 1024; kk += 16) {
        __syncthreads();
        sA[ak + 0][arow] = av.x;
        sA[ak + 1][arow] = av.y;
        *(float4*)&sB[brow][bcol] = bv;
        __syncthreads();
        if (kk + 16 < 1024) {
            av = *(const float2*)(aptr + kk + 16);
            bv = *(const float4*)(bptr + (long)(kk + 16) * 512);
        }
#pragma unroll
        for (int k = 0; k < 16; k++) {
            float2 a2 = *(const float2*)&sA[k][ty << 1];
            float4 b4 = *(const float4*)&sB[k][tx << 2];
            acc[0][0] = fmaf(a2.x, b4.x, acc[0][0]);
            acc[0][1] = fmaf(a2.x, b4.y, acc[0][1]);
            acc[0][2] = fmaf(a2.x, b4.z, acc[0][2]);
            acc[0][3] = fmaf(a2.x, b4.w, acc[0][3]);
            acc[1][0] = fmaf(a2.y, b4.x, acc[1][0]);
            acc[1][1] = fmaf(a2.y, b4.y, acc[1][1]);
            acc[1][2] = fmaf(a2.y, b4.z, acc[1][2]);
            acc[1][3] = fmaf(a2.y, b4.w, acc[1][3]);
        }
    }

    int col0 = bx * 64 + (tx << 2);
    float b0 = g_bias[col0], b1 = g_bias[col0 + 1], b2 = g_bias[col0 + 2], b3 = g_bias[col0 + 3];
    float* pout = g_P + (long)(by * 32 + (ty << 1)) * 512 + col0;
#pragma unroll
    for (int i = 0; i < 2; i++) {
        float4 o;
        o.x = acc[i][0] + b0;
        o.y = acc[i][1] + b1;
        o.z = acc[i][2] + b2;
        o.w = acc[i][3] + b3;
        *(float4*)(pout + (long)i * 512) = o;
    }
}

// ---------------------------------------------------------------------------
// K2: fused head kernel. One block per batch (256 threads).
//     cp.async prefetch of the memory tile overlapped with usage + sort.
// ---------------------------------------------------------------------------
__global__ __launch_bounds__(256) void k_head(
    const float* __restrict__ mem, const float* __restrict__ prw,
    const float* __restrict__ pww, const float* __restrict__ pprec,
    const float* __restrict__ pu, float* __restrict__ out)
{
    extern __shared__ float4 s_mem4[];     // [256 rows][16 float4] = 64 KB
    __shared__ float s_sim[256];
    __shared__ float s_key[256];
    __shared__ int   s_idx[256];
    __shared__ float s_cp[256];
    __shared__ float s_alloc[256];
    __shared__ float s_wwv[256];
    __shared__ float s_wk[64];
    __shared__ float s_r8[8];

    int b = blockIdx.x, t = threadIdx.x;
    int w = t >> 5, l = t & 31, li = l & 15, half = l >> 4;
    const float* P = g_P + (long)b * 512;

    // --- kick off async copy of the old memory tile (hidden behind sort) ---
    const float4* memb = (const float4*)(mem + (long)b * 16384);
    unsigned sbase = (unsigned)__cvta_generic_to_shared(s_mem4);
#pragma unroll
    for (int i = 0; i < 16; i++) {
        asm volatile("cp.async.cg.shared.global [%0], [%1], 16;"
                     :: "r"(sbase + (t + 256 * i) * 16), "l"(memb + t + 256 * i));
    }
    asm volatile("cp.async.commit_group;");

    if (t < 64) s_wk[t] = P[OFF_WK + t];

    // --- usage (independent of memory tile) ---
    float pu_t = pu[(long)b * 256 + t];
    float pww_t = pww[(long)b * 256 + t];
    float uaw = pu_t + (1.f - pu_t) * pww_t;
    float phi = 1.f;
#pragma unroll
    for (int r = 0; r < 4; r++) {
        float fg = sigmoidf_(P[OFF_FG + r]);
        phi *= 1.f - fg * prw[((long)b * 4 + r) * 256 + t];
    }
    float usage = uaw * phi;
    out[O_USAGE + (long)b * 256 + t] = usage;

    // --- allocation: hybrid bitonic sort (shfl j<32, SMEM j>=32) ---
    float u2 = EPSF + (1.f - EPSF) * usage;
    float non = 1.f - u2;
    float key = -non;
    int   idx = t;

    for (int k = 2; k <= 256; k <<= 1) {
        for (int j = k >> 1; j > 0; j >>= 1) {
            float kb; int ib;
            if (j >= 32) {
                __syncthreads();
                s_key[t] = key; s_idx[t] = idx;
                __syncthreads();
                kb = s_key[t ^ j]; ib = s_idx[t ^ j];
            } else {
                kb = __shfl_xor_sync(0xffffffffu, key, j);
                ib = __shfl_xor_sync(0xffffffffu, idx, j);
            }
            bool lower = ((t & j) == 0);
            float ak = lower ? key : kb, bk = lower ? kb : key;
            int   ai = lower ? idx : ib, bi = lower ? ib : idx;
            bool agtb = (ak > bk) || (ak == bk && ai > bi);
            bool up = ((t & k) == 0);
            if (agtb == up) { key = lower ? bk : ak; idx = lower ? bi : ai; }
            else            { key = lower ? ak : bk; idx = lower ? ai : bi; }
        }
    }

    float s_non_t = -key;
    float v = 1.f - s_non_t;
#pragma unroll
    for (int off = 1; off < 32; off <<= 1) {
        float pv = __shfl_up_sync(0xffffffffu, v, off);
        if (l >= off) v *= pv;
    }
    __syncthreads();
    if (l == 31) s_r8[w] = v;
    __syncthreads();
    float pref = 1.f;
#pragma unroll
    for (int k = 0; k < 8; k++) if (k < w) pref *= s_r8[k];
    float incl = v * pref;
    s_cp[t] = incl;
    __syncthreads();
    float excl = (t > 0) ? s_cp[t - 1] : 1.f;
    s_alloc[idx] = s_non_t * excl;

    // --- write key norm + strength ---
    float sq = (t < 64) ? s_wk[t] * s_wk[t] : 0.f;
    float kn = sqrtf(blockSumFast(sq, s_r8));
    float ws = softplusf_(P[OFF_WS]);

    // --- wait for the memory tile ---
    asm volatile("cp.async.wait_group 0;");
    __syncthreads();

    float wk0 = s_wk[4 * li + 0], wk1 = s_wk[4 * li + 1];
    float wk2 = s_wk[4 * li + 2], wk3 = s_wk[4 * li + 3];

    // cosine similarity (2 rows per warp per iteration, 16-lane reductions)
#pragma unroll 4
    for (int i = 0; i < 16; i++) {
        int n = 2 * (w + 8 * i) + half;
        float4 mv = s_mem4[n * 16 + li];
        float d = wk0 * mv.x + wk1 * mv.y + wk2 * mv.z + wk3 * mv.w;
        float q = mv.x * mv.x + mv.y * mv.y + mv.z * mv.z + mv.w * mv.w;
        d = halfSum(d);
        q = halfSum(q);
        if (li == 0) s_sim[n] = d / (kn * sqrtf(q) + EPSF) * ws;
    }
    __syncthreads();

    float sv = s_sim[t];
    float mx = blockMaxFast(sv, s_r8);
    float ev = expf(sv - mx);
    float ssum = blockSumFast(ev, s_r8);
    float content = ev / ssum;

    // --- write weights + precedence ---
    float ag = sigmoidf_(P[OFF_AG]);
    float wg = sigmoidf_(P[OFF_WG]);
    float wwv = wg * (ag * s_alloc[t] + (1.f - ag) * content);
    out[O_WW + (long)b * 256 + t] = wwv;
    g_ww[(long)b * 256 + t] = wwv;
    s_wwv[t] = wwv;
    float sww = blockSumFast(wwv, s_r8);
    out[O_PREC + (long)b * 256 + t] = (1.f - sww) * pprec[(long)b * 256 + t] + wwv;

    if (w < 4) {
        float a = P[OFF_RK + w * 64 + l];
        float c = P[OFF_RK + w * 64 + l + 32];
        float q2 = warpSum(a * a + c * c);
        if (l == 0) g_rkn[(long)b * 4 + w] = sqrtf(q2);
    }
    __syncthreads();

    // --- memory erase/write + rdot/mn2 ---
    float e0 = sigmoidf_(P[OFF_EV + 4 * li + 0]);
    float e1 = sigmoidf_(P[OFF_EV + 4 * li + 1]);
    float e2 = sigmoidf_(P[OFF_EV + 4 * li + 2]);
    float e3 = sigmoidf_(P[OFF_EV + 4 * li + 3]);
    float v0 = P[OFF_WV + 4 * li + 0];
    float v1 = P[OFF_WV + 4 * li + 1];
    float v2 = P[OFF_WV + 4 * li + 2];
    float v3 = P[OFF_WV + 4 * li + 3];
    float rk[4][4];
#pragma unroll
    for (int r = 0; r < 4; r++)
#pragma unroll
        for (int j = 0; j < 4; j++) rk[r][j] = P[OFF_RK + r * 64 + 4 * li + j];

    float4* outm = (float4*)(out + O_MEM) + (long)b * 4096;
#pragma unroll 2
    for (int i = 0; i < 16; i++) {
        int n = 2 * (w + 8 * i) + half;
        float4 mv = s_mem4[n * 16 + li];
        float wwn = s_wwv[n];
        float4 nv;
        nv.x = mv.x * (1.f - wwn * e0) + wwn * v0;
        nv.y = mv.y * (1.f - wwn * e1) + wwn * v1;
        nv.z = mv.z * (1.f - wwn * e2) + wwn * v2;
        nv.w = mv.w * (1.f - wwn * e3) + wwn * v3;
        outm[n * 16 + li] = nv;
        float q  = nv.x * nv.x + nv.y * nv.y + nv.z * nv.z + nv.w * nv.w;
        float d0 = rk[0][0] * nv.x + rk[0][1] * nv.y + rk[0][2] * nv.z + rk[0][3] * nv.w;
        float d1 = rk[1][0] * nv.x + rk[1][1] * nv.y + rk[1][2] * nv.z + rk[1][3] * nv.w;
        float d2 = rk[2][0] * nv.x + rk[2][1] * nv.y + rk[2][2] * nv.z + rk[2][3] * nv.w;
        float d3 = rk[3][0] * nv.x + rk[3][1] * nv.y + rk[3][2] * nv.z + rk[3][3] * nv.w;
        q = halfSum(q); d0 = halfSum(d0); d1 = halfSum(d1); d2 = halfSum(d2); d3 = halfSum(d3);
        if (li == 0) {
            g_mn2[(long)b * 256 + n] = sqrtf(q);
            g_rdot[((long)b * 4 + 0) * 256 + n] = d0;
            g_rdot[((long)b * 4 + 1) * 256 + n] = d1;
            g_rdot[((long)b * 4 + 2) * 256 + n] = d2;
            g_rdot[((long)b * 4 + 3) * 256 + n] = d3;
        }
    }
}

// ---------------------------------------------------------------------------
// K3: link generation, 4 blocks/batch (64 rows each). Prefetched loads +
//     streaming hints. Forward partials inline (residue-transpose reduce).
// ---------------------------------------------------------------------------
__global__ __launch_bounds__(256, 4) void k_link_gen(
    const float* __restrict__ pl, const float* __restrict__ pprec,
    const float* __restrict__ prw, float* __restrict__ out)
{
    int b = blockIdx.x, q = blockIdx.y, t = threadIdx.x;
    int l = t & 31;
    int ty = t >> 6, tx = t & 63;
    int half = (t >> 5) & 1;

    __shared__ float s_ww[256], s_pp[256];
    __shared__ float s_prw[4][256];
    __shared__ float s_fp[4][64][2];
    __shared__ __align__(16) float s_b[16][256];

    s_ww[t] = g_ww[(long)b * 256 + t];
    s_pp[t] = pprec[(long)b * 256 + t];
#pragma unroll
    for (int r = 0; r < 4; r++) s_prw[r][t] = prw[((long)b * 4 + r) * 256 + t];
    __syncthreads();

    int c0 = tx * 4;
    float wwc[4], ppc[4], pr[4][4];
#pragma unroll
    for (int j = 0; j < 4; j++) { wwc[j] = s_ww[c0 + j]; ppc[j] = s_pp[c0 + j]; }
#pragma unroll
    for (int r = 0; r < 4; r++)
#pragma unroll
        for (int j = 0; j < 4; j++) pr[r][j] = s_prw[r][c0 + j];

    float bacc[4][4];
#pragma unroll
    for (int r = 0; r < 4; r++)
#pragma unroll
        for (int j = 0; j < 4; j++) bacc[r][j] = 0.f;

    const float4* plb = (const float4*)(pl + (long)b * 65536);
    float4* lout = (float4*)(out + O_LINK) + (long)b * 16384;

    int base0 = q * 64;
    int m_cur = base0 + ty;
    float4 pv = __ldcs(&plb[m_cur * 64 + tx]);

#pragma unroll
    for (int i = 0; i < 16; i++) {
        int m = base0 + ((i >> 3) << 5) + ty + ((i & 7) << 2);
        int row_local = m - base0;
        float4 cur = pv;
        if (i < 15) {
            int i2 = i + 1;
            int mn = base0 + ((i2 >> 3) << 5) + ty + ((i2 & 7) << 2);
            pv = __ldcs(&plb[mn * 64 + tx]);
        }

        float wwm = s_ww[m];
        float t1 = 1.f - wwm;
        float Lv[4];
        Lv[0] = (t1 - wwc[0]) * cur.x + wwm * ppc[0];
        Lv[1] = (t1 - wwc[1]) * cur.y + wwm * ppc[1];
        Lv[2] = (t1 - wwc[2]) * cur.z + wwm * ppc[2];
        Lv[3] = (t1 - wwc[3]) * cur.w + wwm * ppc[3];
        if (tx == (m >> 2)) Lv[m & 3] = 0.f;
        __stcs(&lout[m * 64 + tx], make_float4(Lv[0], Lv[1], Lv[2], Lv[3]));

#pragma unroll
        for (int r = 0; r < 4; r++) {
            float wpm = s_prw[r][m];
#pragma unroll
            for (int j = 0; j < 4; j++) bacc[r][j] = fmaf(wpm, Lv[j], bacc[r][j]);
        }

        float fp[4];
#pragma unroll
        for (int r = 0; r < 4; r++)
            fp[r] = pr[r][0] * Lv[0] + pr[r][1] * Lv[1]
                  + pr[r][2] * Lv[2] + pr[r][3] * Lv[3];

#pragma unroll
        for (int r = 0; r < 4; r++) {
            fp[r] += __shfl_xor_sync(0xffffffffu, fp[r], 16);
            fp[r] += __shfl_xor_sync(0xffffffffu, fp[r], 8);
        }
        int g = l >> 3;
        float v = (g == 0) ? fp[0] : (g == 1) ? fp[1] : (g == 2) ? fp[2] : fp[3];
        v += __shfl_xor_sync(0xffffffffu, v, 4);
        v += __shfl_xor_sync(0xffffffffu, v, 2);
        v += __shfl_xor_sync(0xffffffffu, v, 1);
        if ((l & 7) == 0) s_fp[g][row_local][half] = v;
    }

#pragma unroll
    for (int r = 0; r < 4; r++)
        *(float4*)&s_b[ty * 4 + r][c0] =
            make_float4(bacc[r][0], bacc[r][1], bacc[r][2], bacc[r][3]);
    __syncthreads();

#pragma unroll
    for (int r = 0; r < 4; r++) {
        float bf = s_b[0 * 4 + r][t] + s_b[1 * 4 + r][t]
                 + s_b[2 * 4 + r][t] + s_b[3 * 4 + r][t];
        g_bpart[(((long)b * 4 + q) * 4 + r) * 256 + t] = bf;
    }

    {
        int r = t >> 6, m = t & 63;
        g_fwd[((long)b * 4 + r) * 256 + q * 64 + m] = s_fp[r][m][0] + s_fp[r][m][1];
    }
}

// ---------------------------------------------------------------------------
// K4: read weights + read_words fused. Single-pass 4-way softmax reductions.
// ---------------------------------------------------------------------------
__global__ __launch_bounds__(256) void k_rw(float* __restrict__ out) {
    int b = blockIdx.x, t = threadIdx.x;
    int w = t >> 5, l = t & 31, li = l & 15, half = l >> 4;
    const float* P = g_P + (long)b * 512;

    __shared__ float s_rw[4][256];
    __shared__ __align__(16) float4 s_part[16][4][16];
    __shared__ float s_m32[32];
    __shared__ float s_s32[32];

    float mn2t = g_mn2[(long)b * 256 + t];
    float sim[4], fw[4], bfin[4];
#pragma unroll
    for (int r = 0; r < 4; r++) {
        bfin[r] = g_bpart[(((long)b * 4 + 0) * 4 + r) * 256 + t]
                + g_bpart[(((long)b * 4 + 1) * 4 + r) * 256 + t]
                + g_bpart[(((long)b * 4 + 2) * 4 + r) * 256 + t]
                + g_bpart[(((long)b * 4 + 3) * 4 + r) * 256 + t];
        fw[r] = g_fwd[((long)b * 4 + r) * 256 + t];
        float rsr = softplusf_(P[OFF_RS + r]);
        float knr = g_rkn[(long)b * 4 + r];
        sim[r] = g_rdot[((long)b * 4 + r) * 256 + t] / (knr * mn2t + EPSF) * rsr;
    }

    // fused 4-way block max
    float m4[4] = {sim[0], sim[1], sim[2], sim[3]};
#pragma unroll
    for (int o = 16; o > 0; o >>= 1)
#pragma unroll
        for (int r = 0; r < 4; r++)
            m4[r] = fmaxf(m4[r], __shfl_xor_sync(0xffffffffu, m4[r], o));
    if (l == 0)
#pragma unroll
        for (int r = 0; r < 4; r++) s_m32[w * 4 + r] = m4[r];
    __syncthreads();
    float mx[4];
#pragma unroll
    for (int r = 0; r < 4; r++) {
        float m = s_m32[r];
#pragma unroll
        for (int k = 1; k < 8; k++) m = fmaxf(m, s_m32[k * 4 + r]);
        mx[r] = m;
    }

    // fused 4-way block sum of exp
    float ev[4], e4[4];
#pragma unroll
    for (int r = 0; r < 4; r++) { ev[r] = expf(sim[r] - mx[r]); e4[r] = ev[r]; }
#pragma unroll
    for (int o = 16; o > 0; o >>= 1)
#pragma unroll
        for (int r = 0; r < 4; r++)
            e4[r] += __shfl_xor_sync(0xffffffffu, e4[r], o);
    if (l == 0)
#pragma unroll
        for (int r = 0; r < 4; r++) s_s32[w * 4 + r] = e4[r];
    __syncthreads();

#pragma unroll
    for (int r = 0; r < 4; r++) {
        float sm = 0.f;
#pragma unroll
        for (int k = 0; k < 8; k++) sm += s_s32[k * 4 + r];
        float contentv = ev[r] / sm;

        float x0 = P[OFF_RM + r * 3 + 0];
        float x1 = P[OFF_RM + r * 3 + 1];
        float x2 = P[OFF_RM + r * 3 + 2];
        float m3 = fmaxf(x0, fmaxf(x1, x2));
        float e0 = expf(x0 - m3), e1 = expf(x1 - m3), e2 = expf(x2 - m3);
        float inv = 1.f / (e0 + e1 + e2);
        float bm = e0 * inv, fm = e1 * inv, cm = e2 * inv;

        float rwv = cm * contentv + fm * fw[r] + bm * bfin[r];
        out[O_RWT + ((long)b * 4 + r) * 256 + t] = rwv;
        s_rw[r][t] = rwv;
    }
    __syncthreads();

    float4 acc[4];
#pragma unroll
    for (int r = 0; r < 4; r++) acc[r] = make_float4(0.f, 0.f, 0.f, 0.f);

    const float4* memv = (const float4*)(out + O_MEM) + (long)b * 4096;
#pragma unroll 4
    for (int i = 0; i < 16; i++) {
        int n = 2 * (w + 8 * i) + half;
        float4 mv = __ldcs(&memv[n * 16 + li]);
#pragma unroll
        for (int r = 0; r < 4; r++) {
            float wr = s_rw[r][n];
            acc[r].x = fmaf(wr, mv.x, acc[r].x);
            acc[r].y = fmaf(wr, mv.y, acc[r].y);
            acc[r].z = fmaf(wr, mv.z, acc[r].z);
            acc[r].w = fmaf(wr, mv.w, acc[r].w);
        }
    }
    int g = w * 2 + half;
#pragma unroll
    for (int r = 0; r < 4; r++) s_part[g][r][li] = acc[r];
    __syncthreads();

    if (t < 64) {
        int r = t >> 4, c = t & 15;
        float4 s = make_float4(0.f, 0.f, 0.f, 0.f);
#pragma unroll
        for (int gg = 0; gg < 16; gg++) {
            float4 p = s_part[gg][r][c];
            s.x += p.x; s.y += p.y; s.z += p.z; s.w += p.w;
        }
        *(float4*)&out[O_RW + (long)b * 256 + r * 64 + 4 * c] = s;
    }
}

// ---------------------------------------------------------------------------
extern "C" void kernel_launch(void* const* d_in, const int* in_sizes, int n_in,
                              void* d_out, int out_size) {
    const float* controller = (const float*)d_in[0];
    const float* memory     = (const float*)d_in[1];
    const float* prw        = (const float*)d_in[2];
    const float* pww        = (const float*)d_in[3];
    const float* pl         = (const float*)d_in[4];
    const float* pprec      = (const float*)d_in[5];
    const float* pu         = (const float*)d_in[6];

    WPtrs p;
    for (int i = 0; i < 10; i++) {
        p.W[i] = (const float*)d_in[7 + 2 * i];
        p.b[i] = (const float*)d_in[8 + 2 * i];
    }
    float* out = (float*)d_out;

    cudaFuncSetAttribute(k_head, cudaFuncAttributeMaxDynamicSharedMemorySize, 65536);

    k_pack<<<2048, 256>>>(p);
    k_gemm<<<dim3(8, 32), 256>>>(controller);
    k_head<<<1024, 256, 65536>>>(memory, prw, pww, pprec, pu, out);
    k_link_gen<<<dim3(1024, 4), 256>>>(pl, pprec, prw, out);
    k_rw<<<1024, 256>>>(out);
}

// round 10
// speedup vs baseline: 1.0809x; 1.0809x over previous
#include <cuda_runtime.h>
#include <math.h>

#define DEV_INLINE __device__ __forceinline__

constexpr float EPSF = 1e-6f;

// packed projection column offsets
constexpr int OFF_WV = 0;
constexpr int OFF_EV = 64;
constexpr int OFF_FG = 128;
constexpr int OFF_AG = 132;
constexpr int OFF_WG = 133;
constexpr int OFF_RM = 134;
constexpr int OFF_WS = 146;
constexpr int OFF_RS = 147;
constexpr int OFF_WK = 151;
constexpr int OFF_RK = 215;

// output offsets (floats): read_words, memory, read_weights, write_weights,
// link, precedence, usage
constexpr long O_RW    = 0L;
constexpr long O_MEM   = 262144L;
constexpr long O_RWT   = 17039360L;
constexpr long O_WW    = 18087936L;
constexpr long O_LINK  = 18350080L;
constexpr long O_PREC  = 85458944L;
constexpr long O_USAGE = 85721088L;

__device__ float g_WP[1024 * 512];
__device__ float g_bias[512];
__device__ float g_P[1024 * 512];
__device__ float g_ww[1024 * 256];
__device__ float g_mn2[1024 * 256];
__device__ float g_rdot[1024 * 4 * 256];
__device__ float g_rkn[1024 * 4];
__device__ float g_fwd[1024 * 4 * 256];          // forward weights [b][r][n]
__device__ float g_bpart[1024 * 4 * 4 * 256];    // backward partials [b][q][r][n]

__constant__ int c_start[11] = {0, 64, 128, 132, 133, 134, 146, 147, 151, 215, 471};

struct WPtrs { const float* W[10]; const float* b[10]; };

DEV_INLINE float sigmoidf_(float x) { return 1.0f / (1.0f + expf(-x)); }
DEV_INLINE float softplusf_(float x) { return x > 20.0f ? x : log1pf(expf(x)); }

DEV_INLINE float warpSum(float v) {
#pragma unroll
    for (int o = 16; o > 0; o >>= 1) v += __shfl_xor_sync(0xffffffffu, v, o);
    return v;
}

DEV_INLINE float halfSum(float v) {
#pragma unroll
    for (int o = 8; o > 0; o >>= 1) v += __shfl_xor_sync(0xffffffffu, v, o);
    return v;
}

DEV_INLINE float blockSumFast(float v, float* s8) {
    __syncthreads();
    v = warpSum(v);
    if ((threadIdx.x & 31) == 0) s8[threadIdx.x >> 5] = v;
    __syncthreads();
    float r = 0.f;
#pragma unroll
    for (int k = 0; k < 8; k++) r += s8[k];
    return r;
}

DEV_INLINE float blockMaxFast(float v, float* s8) {
    __syncthreads();
#pragma unroll
    for (int o = 16; o > 0; o >>= 1) v = fmaxf(v, __shfl_xor_sync(0xffffffffu, v, o));
    if ((threadIdx.x & 31) == 0) s8[threadIdx.x >> 5] = v;
    __syncthreads();
    float r = s8[0];
#pragma unroll
    for (int k = 1; k < 8; k++) r = fmaxf(r, s8[k]);
    return r;
}

// ---------------------------------------------------------------------------
// K0: pack 10 weight matrices into [1024][512] (cols >= 471 zero) + bias row
// ---------------------------------------------------------------------------
__global__ void k_pack(WPtrs p) {
    int idx = blockIdx.x * blockDim.x + threadIdx.x;
    int k = idx >> 9;
    int c = idx & 511;
    float v = 0.f, bv = 0.f;
    if (c < 471) {
        int s = 0;
#pragma unroll
        for (int i = 1; i < 10; i++) if (c >= c_start[i]) s = i;
        int lc = c - c_start[s];
        int od = c_start[s + 1] - c_start[s];
        v = p.W[s][k * od + lc];
        bv = p.b[s][lc];
    }
    g_WP[idx] = v;
    if (k == 0) g_bias[c] = bv;
}

// ---------------------------------------------------------------------------
// K1: P[1024][512] = controller @ WP + bias.  64x64 tile, BK=16, 256 thr.
// ---------------------------------------------------------------------------
__global__ __launch_bounds__(256) void k_gemm(const float* __restrict__ A) {
    __shared__ __align__(16) float sA[16][64];
    __shared__ __align__(16) float sB[16][64];
    int t = threadIdx.x;
    int bx = blockIdx.x, by = blockIdx.y;
    int tx = t & 15, ty = t >> 4;
    int arow = t >> 2, ak = (t & 3) << 2;
    int brow = t >> 4, bcol = (t & 15) << 2;

    const float* aptr = A + (long)(by * 64 + arow) * 1024 + ak;
    const float* bptr = g_WP + (long)brow * 512 + bx * 64 + bcol;

    float acc[4][4];
#pragma unroll
    for (int i = 0; i < 4; i++)
#pragma unroll
        for (int j = 0; j < 4; j++) acc[i][j] = 0.f;

    float4 av = *(const float4*)(aptr);
    float4 bv = *(const float4*)(bptr);

    for (int kk = 0; kk < 1024; kk += 16) {
        __syncthreads();
        sA[ak + 0][arow] = av.x;
        sA[ak + 1][arow] = av.y;
        sA[ak + 2][arow] = av.z;
        sA[ak + 3][arow] = av.w;
        *(float4*)&sB[brow][bcol] = bv;
        __syncthreads();
        if (kk + 16 < 1024) {
            av = *(const float4*)(aptr + kk + 16);
            bv = *(const float4*)(bptr + (long)(kk + 16) * 512);
        }
#pragma unroll
        for (int k = 0; k < 16; k++) {
            float4 a4 = *(const float4*)&sA[k][ty << 2];
            float4 b4 = *(const float4*)&sB[k][tx << 2];
            acc[0][0] = fmaf(a4.x, b4.x, acc[0][0]);
            acc[0][1] = fmaf(a4.x, b4.y, acc[0][1]);
            acc[0][2] = fmaf(a4.x, b4.z, acc[0][2]);
            acc[0][3] = fmaf(a4.x, b4.w, acc[0][3]);
            acc[1][0] = fmaf(a4.y, b4.x, acc[1][0]);
            acc[1][1] = fmaf(a4.y, b4.y, acc[1][1]);
            acc[1][2] = fmaf(a4.y, b4.z, acc[1][2]);
            acc[1][3] = fmaf(a4.y, b4.w, acc[1][3]);
            acc[2][0] = fmaf(a4.z, b4.x, acc[2][0]);
            acc[2][1] = fmaf(a4.z, b4.y, acc[2][1]);
            acc[2][2] = fmaf(a4.z, b4.z, acc[2][2]);
            acc[2][3] = fmaf(a4.z, b4.w, acc[2][3]);
            acc[3][0] = fmaf(a4.w, b4.x, acc[3][0]);
            acc[3][1] = fmaf(a4.w, b4.y, acc[3][1]);
            acc[3][2] = fmaf(a4.w, b4.z, acc[3][2]);
            acc[3][3] = fmaf(a4.w, b4.w, acc[3][3]);
        }
    }

    int col0 = bx * 64 + (tx << 2);
    float b0 = g_bias[col0], b1 = g_bias[col0 + 1], b2 = g_bias[col0 + 2], b3 = g_bias[col0 + 3];
    float* pout = g_P + (long)(by * 64 + (ty << 2)) * 512 + col0;
#pragma unroll
    for (int i = 0; i < 4; i++) {
        float4 o;
        o.x = acc[i][0] + b0;
        o.y = acc[i][1] + b1;
        o.z = acc[i][2] + b2;
        o.w = acc[i][3] + b3;
        *(float4*)(pout + (long)i * 512) = o;
    }
}

// ---------------------------------------------------------------------------
// K2: fused head kernel. One block per batch (256 threads).
//     cp.async prefetch of the memory tile overlapped with usage + sort.
// ---------------------------------------------------------------------------
__global__ __launch_bounds__(256) void k_head(
    const float* __restrict__ mem, const float* __restrict__ prw,
    const float* __restrict__ pww, const float* __restrict__ pprec,
    const float* __restrict__ pu, float* __restrict__ out)
{
    extern __shared__ float4 s_mem4[];     // [256 rows][16 float4] = 64 KB
    __shared__ float s_sim[256];
    __shared__ float s_key[256];
    __shared__ int   s_idx[256];
    __shared__ float s_cp[256];
    __shared__ float s_alloc[256];
    __shared__ float s_wwv[256];
    __shared__ float s_wk[64];
    __shared__ float s_r8[8];

    int b = blockIdx.x, t = threadIdx.x;
    int w = t >> 5, l = t & 31, li = l & 15, half = l >> 4;
    const float* P = g_P + (long)b * 512;

    // --- kick off async copy of the old memory tile (hidden behind sort) ---
    const float4* memb = (const float4*)(mem + (long)b * 16384);
    unsigned sbase = (unsigned)__cvta_generic_to_shared(s_mem4);
#pragma unroll
    for (int i = 0; i < 16; i++) {
        asm volatile("cp.async.cg.shared.global [%0], [%1], 16;"
                     :: "r"(sbase + (t + 256 * i) * 16), "l"(memb + t + 256 * i));
    }
    asm volatile("cp.async.commit_group;");

    if (t < 64) s_wk[t] = P[OFF_WK + t];

    // --- usage (independent of memory tile) ---
    float pu_t = pu[(long)b * 256 + t];
    float pww_t = pww[(long)b * 256 + t];
    float uaw = pu_t + (1.f - pu_t) * pww_t;
    float phi = 1.f;
#pragma unroll
    for (int r = 0; r < 4; r++) {
        float fg = sigmoidf_(P[OFF_FG + r]);
        phi *= 1.f - fg * prw[((long)b * 4 + r) * 256 + t];
    }
    float usage = uaw * phi;
    out[O_USAGE + (long)b * 256 + t] = usage;

    // --- allocation: hybrid bitonic sort (shfl j<32, SMEM j>=32) ---
    float u2 = EPSF + (1.f - EPSF) * usage;
    float non = 1.f - u2;
    float key = -non;
    int   idx = t;

    for (int k = 2; k <= 256; k <<= 1) {
        for (int j = k >> 1; j > 0; j >>= 1) {
            float kb; int ib;
            if (j >= 32) {
                __syncthreads();
                s_key[t] = key; s_idx[t] = idx;
                __syncthreads();
                kb = s_key[t ^ j]; ib = s_idx[t ^ j];
            } else {
                kb = __shfl_xor_sync(0xffffffffu, key, j);
                ib = __shfl_xor_sync(0xffffffffu, idx, j);
            }
            bool lower = ((t & j) == 0);
            float ak = lower ? key : kb, bk = lower ? kb : key;
            int   ai = lower ? idx : ib, bi = lower ? ib : idx;
            bool agtb = (ak > bk) || (ak == bk && ai > bi);
            bool up = ((t & k) == 0);
            if (agtb == up) { key = lower ? bk : ak; idx = lower ? bi : ai; }
            else            { key = lower ? ak : bk; idx = lower ? ai : bi; }
        }
    }

    float s_non_t = -key;
    float v = 1.f - s_non_t;
#pragma unroll
    for (int off = 1; off < 32; off <<= 1) {
        float pv = __shfl_up_sync(0xffffffffu, v, off);
        if (l >= off) v *= pv;
    }
    __syncthreads();
    if (l == 31) s_r8[w] = v;
    __syncthreads();
    float pref = 1.f;
#pragma unroll
    for (int k = 0; k < 8; k++) if (k < w) pref *= s_r8[k];
    float incl = v * pref;
    s_cp[t] = incl;
    __syncthreads();
    float excl = (t > 0) ? s_cp[t - 1] : 1.f;
    s_alloc[idx] = s_non_t * excl;

    // --- write key norm + strength ---
    float sq = (t < 64) ? s_wk[t] * s_wk[t] : 0.f;
    float kn = sqrtf(blockSumFast(sq, s_r8));
    float ws = softplusf_(P[OFF_WS]);

    // --- wait for the memory tile ---
    asm volatile("cp.async.wait_group 0;");
    __syncthreads();

    float wk0 = s_wk[4 * li + 0], wk1 = s_wk[4 * li + 1];
    float wk2 = s_wk[4 * li + 2], wk3 = s_wk[4 * li + 3];

    // cosine similarity (2 rows per warp per iteration, 16-lane reductions)
#pragma unroll 4
    for (int i = 0; i < 16; i++) {
        int n = 2 * (w + 8 * i) + half;
        float4 mv = s_mem4[n * 16 + li];
        float d = wk0 * mv.x + wk1 * mv.y + wk2 * mv.z + wk3 * mv.w;
        float q = mv.x * mv.x + mv.y * mv.y + mv.z * mv.z + mv.w * mv.w;
        d = halfSum(d);
        q = halfSum(q);
        if (li == 0) s_sim[n] = d / (kn * sqrtf(q) + EPSF) * ws;
    }
    __syncthreads();

    float sv = s_sim[t];
    float mx = blockMaxFast(sv, s_r8);
    float ev = expf(sv - mx);
    float ssum = blockSumFast(ev, s_r8);
    float content = ev / ssum;

    // --- write weights + precedence ---
    float ag = sigmoidf_(P[OFF_AG]);
    float wg = sigmoidf_(P[OFF_WG]);
    float wwv = wg * (ag * s_alloc[t] + (1.f - ag) * content);
    out[O_WW + (long)b * 256 + t] = wwv;
    g_ww[(long)b * 256 + t] = wwv;
    s_wwv[t] = wwv;
    float sww = blockSumFast(wwv, s_r8);
    out[O_PREC + (long)b * 256 + t] = (1.f - sww) * pprec[(long)b * 256 + t] + wwv;

    if (w < 4) {
        float a = P[OFF_RK + w * 64 + l];
        float c = P[OFF_RK + w * 64 + l + 32];
        float q2 = warpSum(a * a + c * c);
        if (l == 0) g_rkn[(long)b * 4 + w] = sqrtf(q2);
    }
    __syncthreads();

    // --- memory erase/write + rdot/mn2 ---
    float e0 = sigmoidf_(P[OFF_EV + 4 * li + 0]);
    float e1 = sigmoidf_(P[OFF_EV + 4 * li + 1]);
    float e2 = sigmoidf_(P[OFF_EV + 4 * li + 2]);
    float e3 = sigmoidf_(P[OFF_EV + 4 * li + 3]);
    float v0 = P[OFF_WV + 4 * li + 0];
    float v1 = P[OFF_WV + 4 * li + 1];
    float v2 = P[OFF_WV + 4 * li + 2];
    float v3 = P[OFF_WV + 4 * li + 3];
    float rk[4][4];
#pragma unroll
    for (int r = 0; r < 4; r++)
#pragma unroll
        for (int j = 0; j < 4; j++) rk[r][j] = P[OFF_RK + r * 64 + 4 * li + j];

    float4* outm = (float4*)(out + O_MEM) + (long)b * 4096;
#pragma unroll 2
    for (int i = 0; i < 16; i++) {
        int n = 2 * (w + 8 * i) + half;
        float4 mv = s_mem4[n * 16 + li];
        float wwn = s_wwv[n];
        float4 nv;
        nv.x = mv.x * (1.f - wwn * e0) + wwn * v0;
        nv.y = mv.y * (1.f - wwn * e1) + wwn * v1;
        nv.z = mv.z * (1.f - wwn * e2) + wwn * v2;
        nv.w = mv.w * (1.f - wwn * e3) + wwn * v3;
        outm[n * 16 + li] = nv;
        float q  = nv.x * nv.x + nv.y * nv.y + nv.z * nv.z + nv.w * nv.w;
        float d0 = rk[0][0] * nv.x + rk[0][1] * nv.y + rk[0][2] * nv.z + rk[0][3] * nv.w;
        float d1 = rk[1][0] * nv.x + rk[1][1] * nv.y + rk[1][2] * nv.z + rk[1][3] * nv.w;
        float d2 = rk[2][0] * nv.x + rk[2][1] * nv.y + rk[2][2] * nv.z + rk[2][3] * nv.w;
        float d3 = rk[3][0] * nv.x + rk[3][1] * nv.y + rk[3][2] * nv.z + rk[3][3] * nv.w;
        q = halfSum(q); d0 = halfSum(d0); d1 = halfSum(d1); d2 = halfSum(d2); d3 = halfSum(d3);
        if (li == 0) {
            g_mn2[(long)b * 256 + n] = sqrtf(q);
            g_rdot[((long)b * 4 + 0) * 256 + n] = d0;
            g_rdot[((long)b * 4 + 1) * 256 + n] = d1;
            g_rdot[((long)b * 4 + 2) * 256 + n] = d2;
            g_rdot[((long)b * 4 + 3) * 256 + n] = d3;
        }
    }
}

// ---------------------------------------------------------------------------
// K3: link generation, 4 blocks/batch (64 rows each). Prefetched loads +
//     streaming hints. Forward partials inline (residue-transpose reduce).
// ---------------------------------------------------------------------------
__global__ __launch_bounds__(256, 4) void k_link_gen(
    const float* __restrict__ pl, const float* __restrict__ pprec,
    const float* __restrict__ prw, float* __restrict__ out)
{
    int b = blockIdx.x, q = blockIdx.y, t = threadIdx.x;
    int l = t & 31;
    int ty = t >> 6, tx = t & 63;
    int half = (t >> 5) & 1;

    __shared__ float s_ww[256], s_pp[256];
    __shared__ float s_prw[4][256];
    __shared__ float s_fp[4][64][2];
    __shared__ __align__(16) float s_b[16][256];

    s_ww[t] = g_ww[(long)b * 256 + t];
    s_pp[t] = pprec[(long)b * 256 + t];
#pragma unroll
    for (int r = 0; r < 4; r++) s_prw[r][t] = prw[((long)b * 4 + r) * 256 + t];
    __syncthreads();

    int c0 = tx * 4;
    float wwc[4], ppc[4], pr[4][4];
#pragma unroll
    for (int j = 0; j < 4; j++) { wwc[j] = s_ww[c0 + j]; ppc[j] = s_pp[c0 + j]; }
#pragma unroll
    for (int r = 0; r < 4; r++)
#pragma unroll
        for (int j = 0; j < 4; j++) pr[r][j] = s_prw[r][c0 + j];

    float bacc[4][4];
#pragma unroll
    for (int r = 0; r < 4; r++)
#pragma unroll
        for (int j = 0; j < 4; j++) bacc[r][j] = 0.f;

    const float4* plb = (const float4*)(pl + (long)b * 65536);
    float4* lout = (float4*)(out + O_LINK) + (long)b * 16384;

    int base0 = q * 64;
    int m_cur = base0 + ty;
    float4 pv = __ldcs(&plb[m_cur * 64 + tx]);

#pragma unroll
    for (int i = 0; i < 16; i++) {
        int m = base0 + ((i >> 3) << 5) + ty + ((i & 7) << 2);
        int row_local = m - base0;
        float4 cur = pv;
        if (i < 15) {
            int i2 = i + 1;
            int mn = base0 + ((i2 >> 3) << 5) + ty + ((i2 & 7) << 2);
            pv = __ldcs(&plb[mn * 64 + tx]);
        }

        float wwm = s_ww[m];
        float t1 = 1.f - wwm;
        float Lv[4];
        Lv[0] = (t1 - wwc[0]) * cur.x + wwm * ppc[0];
        Lv[1] = (t1 - wwc[1]) * cur.y + wwm * ppc[1];
        Lv[2] = (t1 - wwc[2]) * cur.z + wwm * ppc[2];
        Lv[3] = (t1 - wwc[3]) * cur.w + wwm * ppc[3];
        if (tx == (m >> 2)) Lv[m & 3] = 0.f;
        __stcs(&lout[m * 64 + tx], make_float4(Lv[0], Lv[1], Lv[2], Lv[3]));

#pragma unroll
        for (int r = 0; r < 4; r++) {
            float wpm = s_prw[r][m];
#pragma unroll
            for (int j = 0; j < 4; j++) bacc[r][j] = fmaf(wpm, Lv[j], bacc[r][j]);
        }

        float fp[4];
#pragma unroll
        for (int r = 0; r < 4; r++)
            fp[r] = pr[r][0] * Lv[0] + pr[r][1] * Lv[1]
                  + pr[r][2] * Lv[2] + pr[r][3] * Lv[3];

#pragma unroll
        for (int r = 0; r < 4; r++) {
            fp[r] += __shfl_xor_sync(0xffffffffu, fp[r], 16);
            fp[r] += __shfl_xor_sync(0xffffffffu, fp[r], 8);
        }
        int g = l >> 3;
        float v = (g == 0) ? fp[0] : (g == 1) ? fp[1] : (g == 2) ? fp[2] : fp[3];
        v += __shfl_xor_sync(0xffffffffu, v, 4);
        v += __shfl_xor_sync(0xffffffffu, v, 2);
        v += __shfl_xor_sync(0xffffffffu, v, 1);
        if ((l & 7) == 0) s_fp[g][row_local][half] = v;
    }

#pragma unroll
    for (int r = 0; r < 4; r++)
        *(float4*)&s_b[ty * 4 + r][c0] =
            make_float4(bacc[r][0], bacc[r][1], bacc[r][2], bacc[r][3]);
    __syncthreads();

#pragma unroll
    for (int r = 0; r < 4; r++) {
        float bf = s_b[0 * 4 + r][t] + s_b[1 * 4 + r][t]
                 + s_b[2 * 4 + r][t] + s_b[3 * 4 + r][t];
        g_bpart[(((long)b * 4 + q) * 4 + r) * 256 + t] = bf;
    }

    {
        int r = t >> 6, m = t & 63;
        g_fwd[((long)b * 4 + r) * 256 + q * 64 + m] = s_fp[r][m][0] + s_fp[r][m][1];
    }
}

// ---------------------------------------------------------------------------
// K4: read weights + read_words fused. Single-pass 4-way softmax reductions.
// ---------------------------------------------------------------------------
__global__ __launch_bounds__(256) void k_rw(float* __restrict__ out) {
    int b = blockIdx.x, t = threadIdx.x;
    int w = t >> 5, l = t & 31, li = l & 15, half = l >> 4;
    const float* P = g_P + (long)b * 512;

    __shared__ float s_rw[4][256];
    __shared__ __align__(16) float4 s_part[16][4][16];
    __shared__ float s_m32[32];
    __shared__ float s_s32[32];

    float mn2t = g_mn2[(long)b * 256 + t];
    float sim[4], fw[4], bfin[4];
#pragma unroll
    for (int r = 0; r < 4; r++) {
        bfin[r] = g_bpart[(((long)b * 4 + 0) * 4 + r) * 256 + t]
                + g_bpart[(((long)b * 4 + 1) * 4 + r) * 256 + t]
                + g_bpart[(((long)b * 4 + 2) * 4 + r) * 256 + t]
                + g_bpart[(((long)b * 4 + 3) * 4 + r) * 256 + t];
        fw[r] = g_fwd[((long)b * 4 + r) * 256 + t];
        float rsr = softplusf_(P[OFF_RS + r]);
        float knr = g_rkn[(long)b * 4 + r];
        sim[r] = g_rdot[((long)b * 4 + r) * 256 + t] / (knr * mn2t + EPSF) * rsr;
    }

    // fused 4-way block max
    float m4[4] = {sim[0], sim[1], sim[2], sim[3]};
#pragma unroll
    for (int o = 16; o > 0; o >>= 1)
#pragma unroll
        for (int r = 0; r < 4; r++)
            m4[r] = fmaxf(m4[r], __shfl_xor_sync(0xffffffffu, m4[r], o));
    if (l == 0)
#pragma unroll
        for (int r = 0; r < 4; r++) s_m32[w * 4 + r] = m4[r];
    __syncthreads();
    float mx[4];
#pragma unroll
    for (int r = 0; r < 4; r++) {
        float m = s_m32[r];
#pragma unroll
        for (int k = 1; k < 8; k++) m = fmaxf(m, s_m32[k * 4 + r]);
        mx[r] = m;
    }

    // fused 4-way block sum of exp
    float ev[4], e4[4];
#pragma unroll
    for (int r = 0; r < 4; r++) { ev[r] = expf(sim[r] - mx[r]); e4[r] = ev[r]; }
#pragma unroll
    for (int o = 16; o > 0; o >>= 1)
#pragma unroll
        for (int r = 0; r < 4; r++)
            e4[r] += __shfl_xor_sync(0xffffffffu, e4[r], o);
    if (l == 0)
#pragma unroll
        for (int r = 0; r < 4; r++) s_s32[w * 4 + r] = e4[r];
    __syncthreads();

#pragma unroll
    for (int r = 0; r < 4; r++) {
        float sm = 0.f;
#pragma unroll
        for (int k = 0; k < 8; k++) sm += s_s32[k * 4 + r];
        float contentv = ev[r] / sm;

        float x0 = P[OFF_RM + r * 3 + 0];
        float x1 = P[OFF_RM + r * 3 + 1];
        float x2 = P[OFF_RM + r * 3 + 2];
        float m3 = fmaxf(x0, fmaxf(x1, x2));
        float e0 = expf(x0 - m3), e1 = expf(x1 - m3), e2 = expf(x2 - m3);
        float inv = 1.f / (e0 + e1 + e2);
        float bm = e0 * inv, fm = e1 * inv, cm = e2 * inv;

        float rwv = cm * contentv + fm * fw[r] + bm * bfin[r];
        out[O_RWT + ((long)b * 4 + r) * 256 + t] = rwv;
        s_rw[r][t] = rwv;
    }
    __syncthreads();

    float4 acc[4];
#pragma unroll
    for (int r = 0; r < 4; r++) acc[r] = make_float4(0.f, 0.f, 0.f, 0.f);

    const float4* memv = (const float4*)(out + O_MEM) + (long)b * 4096;
#pragma unroll 4
    for (int i = 0; i < 16; i++) {
        int n = 2 * (w + 8 * i) + half;
        float4 mv = __ldcs(&memv[n * 16 + li]);
#pragma unroll
        for (int r = 0; r < 4; r++) {
            float wr = s_rw[r][n];
            acc[r].x = fmaf(wr, mv.x, acc[r].x);
            acc[r].y = fmaf(wr, mv.y, acc[r].y);
            acc[r].z = fmaf(wr, mv.z, acc[r].z);
            acc[r].w = fmaf(wr, mv.w, acc[r].w);
        }
    }
    int g = w * 2 + half;
#pragma unroll
    for (int r = 0; r < 4; r++) s_part[g][r][li] = acc[r];
    __syncthreads();

    if (t < 64) {
        int r = t >> 4, c = t & 15;
        float4 s = make_float4(0.f, 0.f, 0.f, 0.f);
#pragma unroll
        for (int gg = 0; gg < 16; gg++) {
            float4 p = s_part[gg][r][c];
            s.x += p.x; s.y += p.y; s.z += p.z; s.w += p.w;
        }
        *(float4*)&out[O_RW + (long)b * 256 + r * 64 + 4 * c] = s;
    }
}

// ---------------------------------------------------------------------------
extern "C" void kernel_launch(void* const* d_in, const int* in_sizes, int n_in,
                              void* d_out, int out_size) {
    const float* controller = (const float*)d_in[0];
    const float* memory     = (const float*)d_in[1];
    const float* prw        = (const float*)d_in[2];
    const float* pww        = (const float*)d_in[3];
    const float* pl         = (const float*)d_in[4];
    const float* pprec      = (const float*)d_in[5];
    const float* pu         = (const float*)d_in[6];

    WPtrs p;
    for (int i = 0; i < 10; i++) {
        p.W[i] = (const float*)d_in[7 + 2 * i];
        p.b[i] = (const float*)d_in[8 + 2 * i];
    }
    float* out = (float*)d_out;

    cudaFuncSetAttribute(k_head, cudaFuncAttributeMaxDynamicSharedMemorySize, 65536);

    k_pack<<<2048, 256>>>(p);
    k_gemm<<<dim3(8, 16), 256>>>(controller);
    k_head<<<1024, 256, 65536>>>(memory, prw, pww, pprec, pu, out);
    k_link_gen<<<dim3(1024, 4), 256>>>(pl, pprec, prw, out);
    k_rw<<<1024, 256>>>(out);
}

// round 11
// speedup vs baseline: 1.0819x; 1.0009x over previous
#include <cuda_runtime.h>
#include <math.h>

#define DEV_INLINE __device__ __forceinline__

constexpr float EPSF = 1e-6f;

// packed projection column offsets
constexpr int OFF_WV = 0;
constexpr int OFF_EV = 64;
constexpr int OFF_FG = 128;
constexpr int OFF_AG = 132;
constexpr int OFF_WG = 133;
constexpr int OFF_RM = 134;
constexpr int OFF_WS = 146;
constexpr int OFF_RS = 147;
constexpr int OFF_WK = 151;
constexpr int OFF_RK = 215;

// output offsets (floats): read_words, memory, read_weights, write_weights,
// link, precedence, usage
constexpr long O_RW    = 0L;
constexpr long O_MEM   = 262144L;
constexpr long O_RWT   = 17039360L;
constexpr long O_WW    = 18087936L;
constexpr long O_LINK  = 18350080L;
constexpr long O_PREC  = 85458944L;
constexpr long O_USAGE = 85721088L;

__device__ float g_WP[1024 * 512];
__device__ float g_bias[512];
__device__ float g_P[1024 * 512];
__device__ float g_ww[1024 * 256];
__device__ float g_mn2[1024 * 256];
__device__ float g_rdot[1024 * 4 * 256];
__device__ float g_rkn[1024 * 4];
__device__ float g_fwd[1024 * 4 * 256];          // forward weights [b][r][n]
__device__ float g_bpart[1024 * 4 * 4 * 256];    // backward partials [b][q][r][n]

__constant__ int c_start[11] = {0, 64, 128, 132, 133, 134, 146, 147, 151, 215, 471};

struct WPtrs { const float* W[10]; const float* b[10]; };

DEV_INLINE float sigmoidf_(float x) { return 1.0f / (1.0f + expf(-x)); }
DEV_INLINE float softplusf_(float x) { return x > 20.0f ? x : log1pf(expf(x)); }

DEV_INLINE float warpSum(float v) {
#pragma unroll
    for (int o = 16; o > 0; o >>= 1) v += __shfl_xor_sync(0xffffffffu, v, o);
    return v;
}

DEV_INLINE float halfSum(float v) {
#pragma unroll
    for (int o = 8; o > 0; o >>= 1) v += __shfl_xor_sync(0xffffffffu, v, o);
    return v;
}

DEV_INLINE float blockSumFast(float v, float* s8) {
    __syncthreads();
    v = warpSum(v);
    if ((threadIdx.x & 31) == 0) s8[threadIdx.x >> 5] = v;
    __syncthreads();
    float r = 0.f;
#pragma unroll
    for (int k = 0; k < 8; k++) r += s8[k];
    return r;
}

DEV_INLINE float blockMaxFast(float v, float* s8) {
    __syncthreads();
#pragma unroll
    for (int o = 16; o > 0; o >>= 1) v = fmaxf(v, __shfl_xor_sync(0xffffffffu, v, o));
    if ((threadIdx.x & 31) == 0) s8[threadIdx.x >> 5] = v;
    __syncthreads();
    float r = s8[0];
#pragma unroll
    for (int k = 1; k < 8; k++) r = fmaxf(r, s8[k]);
    return r;
}

// packed f32x2 helpers (Blackwell): d = a2 * b2 + d, lane-wise
#define FMA_F32X2(d, a, b) \
    asm("fma.rn.f32x2 %0, %1, %2, %0;" : "+l"(d) : "l"(a), "l"(b))
#define PACK2(out, lo, hi) \
    asm("mov.b64 %0, {%1, %2};" : "=l"(out) : "f"(lo), "f"(hi))

// ---------------------------------------------------------------------------
// K0: pack 10 weight matrices into [1024][512] (cols >= 471 zero) + bias row
// ---------------------------------------------------------------------------
__global__ void k_pack(WPtrs p) {
    int idx = blockIdx.x * blockDim.x + threadIdx.x;
    int k = idx >> 9;
    int c = idx & 511;
    float v = 0.f, bv = 0.f;
    if (c < 471) {
        int s = 0;
#pragma unroll
        for (int i = 1; i < 10; i++) if (c >= c_start[i]) s = i;
        int lc = c - c_start[s];
        int od = c_start[s + 1] - c_start[s];
        v = p.W[s][k * od + lc];
        bv = p.b[s][lc];
    }
    g_WP[idx] = v;
    if (k == 0) g_bias[c] = bv;
}

// ---------------------------------------------------------------------------
// K1: P[1024][512] = controller @ WP + bias.  64x64 tile, BK=16, 256 thr.
//     Inner loop uses packed fma.rn.f32x2 (2 MACs/instr) - FMA pipe halved.
// ---------------------------------------------------------------------------
__global__ __launch_bounds__(256) void k_gemm(const float* __restrict__ A) {
    __shared__ __align__(16) float sA[16][64];
    __shared__ __align__(16) float sB[16][64];
    int t = threadIdx.x;
    int bx = blockIdx.x, by = blockIdx.y;
    int tx = t & 15, ty = t >> 4;
    int arow = t >> 2, ak = (t & 3) << 2;
    int brow = t >> 4, bcol = (t & 15) << 2;

    const float* aptr = A + (long)(by * 64 + arow) * 1024 + ak;
    const float* bptr = g_WP + (long)brow * 512 + bx * 64 + bcol;

    // packed accumulators: acc01[i] = (C[i][0], C[i][1]), acc23[i] = (C[i][2], C[i][3])
    unsigned long long acc01[4], acc23[4];
#pragma unroll
    for (int i = 0; i < 4; i++) { acc01[i] = 0ull; acc23[i] = 0ull; }

    float4 av = *(const float4*)(aptr);
    float4 bv = *(const float4*)(bptr);

    for (int kk = 0; kk < 1024; kk += 16) {
        __syncthreads();
        sA[ak + 0][arow] = av.x;
        sA[ak + 1][arow] = av.y;
        sA[ak + 2][arow] = av.z;
        sA[ak + 3][arow] = av.w;
        *(float4*)&sB[brow][bcol] = bv;
        __syncthreads();
        if (kk + 16 < 1024) {
            av = *(const float4*)(aptr + kk + 16);
            bv = *(const float4*)(bptr + (long)(kk + 16) * 512);
        }
#pragma unroll
        for (int k = 0; k < 16; k++) {
            float4 a4 = *(const float4*)&sA[k][ty << 2];
            float4 b4 = *(const float4*)&sB[k][tx << 2];
            unsigned long long b01, b23;
            PACK2(b01, b4.x, b4.y);
            PACK2(b23, b4.z, b4.w);
            unsigned long long aa0, aa1, aa2, aa3;
            PACK2(aa0, a4.x, a4.x);
            PACK2(aa1, a4.y, a4.y);
            PACK2(aa2, a4.z, a4.z);
            PACK2(aa3, a4.w, a4.w);
            FMA_F32X2(acc01[0], aa0, b01);
            FMA_F32X2(acc23[0], aa0, b23);
            FMA_F32X2(acc01[1], aa1, b01);
            FMA_F32X2(acc23[1], aa1, b23);
            FMA_F32X2(acc01[2], aa2, b01);
            FMA_F32X2(acc23[2], aa2, b23);
            FMA_F32X2(acc01[3], aa3, b01);
            FMA_F32X2(acc23[3], aa3, b23);
        }
    }

    int col0 = bx * 64 + (tx << 2);
    float b0 = g_bias[col0], b1 = g_bias[col0 + 1], b2 = g_bias[col0 + 2], b3 = g_bias[col0 + 3];
    float* pout = g_P + (long)(by * 64 + (ty << 2)) * 512 + col0;
#pragma unroll
    for (int i = 0; i < 4; i++) {
        float2 lo = *(float2*)&acc01[i];
        float2 hi = *(float2*)&acc23[i];
        float4 o;
        o.x = lo.x + b0;
        o.y = lo.y + b1;
        o.z = hi.x + b2;
        o.w = hi.y + b3;
        *(float4*)(pout + (long)i * 512) = o;
    }
}

// ---------------------------------------------------------------------------
// K2: fused head kernel. One block per batch (256 threads).
//     cp.async prefetch of the memory tile overlapped with usage + sort.
// ---------------------------------------------------------------------------
__global__ __launch_bounds__(256) void k_head(
    const float* __restrict__ mem, const float* __restrict__ prw,
    const float* __restrict__ pww, const float* __restrict__ pprec,
    const float* __restrict__ pu, float* __restrict__ out)
{
    extern __shared__ float4 s_mem4[];     // [256 rows][16 float4] = 64 KB
    __shared__ float s_sim[256];
    __shared__ float s_key[256];
    __shared__ int   s_idx[256];
    __shared__ float s_cp[256];
    __shared__ float s_alloc[256];
    __shared__ float s_wwv[256];
    __shared__ float s_wk[64];
    __shared__ float s_r8[8];

    int b = blockIdx.x, t = threadIdx.x;
    int w = t >> 5, l = t & 31, li = l & 15, half = l >> 4;
    const float* P = g_P + (long)b * 512;

    // --- kick off async copy of the old memory tile (hidden behind sort) ---
    const float4* memb = (const float4*)(mem + (long)b * 16384);
    unsigned sbase = (unsigned)__cvta_generic_to_shared(s_mem4);
#pragma unroll
    for (int i = 0; i < 16; i++) {
        asm volatile("cp.async.cg.shared.global [%0], [%1], 16;"
                     :: "r"(sbase + (t + 256 * i) * 16), "l"(memb + t + 256 * i));
    }
    asm volatile("cp.async.commit_group;");

    if (t < 64) s_wk[t] = P[OFF_WK + t];

    // --- usage (independent of memory tile) ---
    float pu_t = pu[(long)b * 256 + t];
    float pww_t = pww[(long)b * 256 + t];
    float uaw = pu_t + (1.f - pu_t) * pww_t;
    float phi = 1.f;
#pragma unroll
    for (int r = 0; r < 4; r++) {
        float fg = sigmoidf_(P[OFF_FG + r]);
        phi *= 1.f - fg * prw[((long)b * 4 + r) * 256 + t];
    }
    float usage = uaw * phi;
    out[O_USAGE + (long)b * 256 + t] = usage;

    // --- allocation: hybrid bitonic sort (shfl j<32, SMEM j>=32) ---
    float u2 = EPSF + (1.f - EPSF) * usage;
    float non = 1.f - u2;
    float key = -non;
    int   idx = t;

    for (int k = 2; k <= 256; k <<= 1) {
        for (int j = k >> 1; j > 0; j >>= 1) {
            float kb; int ib;
            if (j >= 32) {
                __syncthreads();
                s_key[t] = key; s_idx[t] = idx;
                __syncthreads();
                kb = s_key[t ^ j]; ib = s_idx[t ^ j];
            } else {
                kb = __shfl_xor_sync(0xffffffffu, key, j);
                ib = __shfl_xor_sync(0xffffffffu, idx, j);
            }
            bool lower = ((t & j) == 0);
            float ak = lower ? key : kb, bk = lower ? kb : key;
            int   ai = lower ? idx : ib, bi = lower ? ib : idx;
            bool agtb = (ak > bk) || (ak == bk && ai > bi);
            bool up = ((t & k) == 0);
            if (agtb == up) { key = lower ? bk : ak; idx = lower ? bi : ai; }
            else            { key = lower ? ak : bk; idx = lower ? ai : bi; }
        }
    }

    float s_non_t = -key;
    float v = 1.f - s_non_t;
#pragma unroll
    for (int off = 1; off < 32; off <<= 1) {
        float pv = __shfl_up_sync(0xffffffffu, v, off);
        if (l >= off) v *= pv;
    }
    __syncthreads();
    if (l == 31) s_r8[w] = v;
    __syncthreads();
    float pref = 1.f;
#pragma unroll
    for (int k = 0; k < 8; k++) if (k < w) pref *= s_r8[k];
    float incl = v * pref;
    s_cp[t] = incl;
    __syncthreads();
    float excl = (t > 0) ? s_cp[t - 1] : 1.f;
    s_alloc[idx] = s_non_t * excl;

    // --- write key norm + strength ---
    float sq = (t < 64) ? s_wk[t] * s_wk[t] : 0.f;
    float kn = sqrtf(blockSumFast(sq, s_r8));
    float ws = softplusf_(P[OFF_WS]);

    // --- wait for the memory tile ---
    asm volatile("cp.async.wait_group 0;");
    __syncthreads();

    float wk0 = s_wk[4 * li + 0], wk1 = s_wk[4 * li + 1];
    float wk2 = s_wk[4 * li + 2], wk3 = s_wk[4 * li + 3];

    // cosine similarity (2 rows per warp per iteration, 16-lane reductions)
#pragma unroll 4
    for (int i = 0; i < 16; i++) {
        int n = 2 * (w + 8 * i) + half;
        float4 mv = s_mem4[n * 16 + li];
        float d = wk0 * mv.x + wk1 * mv.y + wk2 * mv.z + wk3 * mv.w;
        float q = mv.x * mv.x + mv.y * mv.y + mv.z * mv.z + mv.w * mv.w;
        d = halfSum(d);
        q = halfSum(q);
        if (li == 0) s_sim[n] = d / (kn * sqrtf(q) + EPSF) * ws;
    }
    __syncthreads();

    float sv = s_sim[t];
    float mx = blockMaxFast(sv, s_r8);
    float ev = expf(sv - mx);
    float ssum = blockSumFast(ev, s_r8);
    float content = ev / ssum;

    // --- write weights + precedence ---
    float ag = sigmoidf_(P[OFF_AG]);
    float wg = sigmoidf_(P[OFF_WG]);
    float wwv = wg * (ag * s_alloc[t] + (1.f - ag) * content);
    out[O_WW + (long)b * 256 + t] = wwv;
    g_ww[(long)b * 256 + t] = wwv;
    s_wwv[t] = wwv;
    float sww = blockSumFast(wwv, s_r8);
    out[O_PREC + (long)b * 256 + t] = (1.f - sww) * pprec[(long)b * 256 + t] + wwv;

    if (w < 4) {
        float a = P[OFF_RK + w * 64 + l];
        float c = P[OFF_RK + w * 64 + l + 32];
        float q2 = warpSum(a * a + c * c);
        if (l == 0) g_rkn[(long)b * 4 + w] = sqrtf(q2);
    }
    __syncthreads();

    // --- memory erase/write + rdot/mn2 ---
    float e0 = sigmoidf_(P[OFF_EV + 4 * li + 0]);
    float e1 = sigmoidf_(P[OFF_EV + 4 * li + 1]);
    float e2 = sigmoidf_(P[OFF_EV + 4 * li + 2]);
    float e3 = sigmoidf_(P[OFF_EV + 4 * li + 3]);
    float v0 = P[OFF_WV + 4 * li + 0];
    float v1 = P[OFF_WV + 4 * li + 1];
    float v2 = P[OFF_WV + 4 * li + 2];
    float v3 = P[OFF_WV + 4 * li + 3];
    float rk[4][4];
#pragma unroll
    for (int r = 0; r < 4; r++)
#pragma unroll
        for (int j = 0; j < 4; j++) rk[r][j] = P[OFF_RK + r * 64 + 4 * li + j];

    float4* outm = (float4*)(out + O_MEM) + (long)b * 4096;
#pragma unroll 2
    for (int i = 0; i < 16; i++) {
        int n = 2 * (w + 8 * i) + half;
        float4 mv = s_mem4[n * 16 + li];
        float wwn = s_wwv[n];
        float4 nv;
        nv.x = mv.x * (1.f - wwn * e0) + wwn * v0;
        nv.y = mv.y * (1.f - wwn * e1) + wwn * v1;
        nv.z = mv.z * (1.f - wwn * e2) + wwn * v2;
        nv.w = mv.w * (1.f - wwn * e3) + wwn * v3;
        outm[n * 16 + li] = nv;
        float q  = nv.x * nv.x + nv.y * nv.y + nv.z * nv.z + nv.w * nv.w;
        float d0 = rk[0][0] * nv.x + rk[0][1] * nv.y + rk[0][2] * nv.z + rk[0][3] * nv.w;
        float d1 = rk[1][0] * nv.x + rk[1][1] * nv.y + rk[1][2] * nv.z + rk[1][3] * nv.w;
        float d2 = rk[2][0] * nv.x + rk[2][1] * nv.y + rk[2][2] * nv.z + rk[2][3] * nv.w;
        float d3 = rk[3][0] * nv.x + rk[3][1] * nv.y + rk[3][2] * nv.z + rk[3][3] * nv.w;
        q = halfSum(q); d0 = halfSum(d0); d1 = halfSum(d1); d2 = halfSum(d2); d3 = halfSum(d3);
        if (li == 0) {
            g_mn2[(long)b * 256 + n] = sqrtf(q);
            g_rdot[((long)b * 4 + 0) * 256 + n] = d0;
            g_rdot[((long)b * 4 + 1) * 256 + n] = d1;
            g_rdot[((long)b * 4 + 2) * 256 + n] = d2;
            g_rdot[((long)b * 4 + 3) * 256 + n] = d3;
        }
    }
}

// ---------------------------------------------------------------------------
// K3: link generation, 4 blocks/batch (64 rows each). Prefetched loads +
//     streaming hints. Forward partials inline (residue-transpose reduce).
// ---------------------------------------------------------------------------
__global__ __launch_bounds__(256, 4) void k_link_gen(
    const float* __restrict__ pl, const float* __restrict__ pprec,
    const float* __restrict__ prw, float* __restrict__ out)
{
    int b = blockIdx.x, q = blockIdx.y, t = threadIdx.x;
    int l = t & 31;
    int ty = t >> 6, tx = t & 63;
    int half = (t >> 5) & 1;

    __shared__ float s_ww[256], s_pp[256];
    __shared__ float s_prw[4][256];
    __shared__ float s_fp[4][64][2];
    __shared__ __align__(16) float s_b[16][256];

    s_ww[t] = g_ww[(long)b * 256 + t];
    s_pp[t] = pprec[(long)b * 256 + t];
#pragma unroll
    for (int r = 0; r < 4; r++) s_prw[r][t] = prw[((long)b * 4 + r) * 256 + t];
    __syncthreads();

    int c0 = tx * 4;
    float wwc[4], ppc[4], pr[4][4];
#pragma unroll
    for (int j = 0; j < 4; j++) { wwc[j] = s_ww[c0 + j]; ppc[j] = s_pp[c0 + j]; }
#pragma unroll
    for (int r = 0; r < 4; r++)
#pragma unroll
        for (int j = 0; j < 4; j++) pr[r][j] = s_prw[r][c0 + j];

    float bacc[4][4];
#pragma unroll
    for (int r = 0; r < 4; r++)
#pragma unroll
        for (int j = 0; j < 4; j++) bacc[r][j] = 0.f;

    const float4* plb = (const float4*)(pl + (long)b * 65536);
    float4* lout = (float4*)(out + O_LINK) + (long)b * 16384;

    int base0 = q * 64;
    int m_cur = base0 + ty;
    float4 pv = __ldcs(&plb[m_cur * 64 + tx]);

#pragma unroll
    for (int i = 0; i < 16; i++) {
        int m = base0 + ((i >> 3) << 5) + ty + ((i & 7) << 2);
        int row_local = m - base0;
        float4 cur = pv;
        if (i < 15) {
            int i2 = i + 1;
            int mn = base0 + ((i2 >> 3) << 5) + ty + ((i2 & 7) << 2);
            pv = __ldcs(&plb[mn * 64 + tx]);
        }

        float wwm = s_ww[m];
        float t1 = 1.f - wwm;
        float Lv[4];
        Lv[0] = (t1 - wwc[0]) * cur.x + wwm * ppc[0];
        Lv[1] = (t1 - wwc[1]) * cur.y + wwm * ppc[1];
        Lv[2] = (t1 - wwc[2]) * cur.z + wwm * ppc[2];
        Lv[3] = (t1 - wwc[3]) * cur.w + wwm * ppc[3];
        if (tx == (m >> 2)) Lv[m & 3] = 0.f;
        __stcs(&lout[m * 64 + tx], make_float4(Lv[0], Lv[1], Lv[2], Lv[3]));

#pragma unroll
        for (int r = 0; r < 4; r++) {
            float wpm = s_prw[r][m];
#pragma unroll
            for (int j = 0; j < 4; j++) bacc[r][j] = fmaf(wpm, Lv[j], bacc[r][j]);
        }

        float fp[4];
#pragma unroll
        for (int r = 0; r < 4; r++)
            fp[r] = pr[r][0] * Lv[0] + pr[r][1] * Lv[1]
                  + pr[r][2] * Lv[2] + pr[r][3] * Lv[3];

#pragma unroll
        for (int r = 0; r < 4; r++) {
            fp[r] += __shfl_xor_sync(0xffffffffu, fp[r], 16);
            fp[r] += __shfl_xor_sync(0xffffffffu, fp[r], 8);
        }
        int g = l >> 3;
        float v = (g == 0) ? fp[0] : (g == 1) ? fp[1] : (g == 2) ? fp[2] : fp[3];
        v += __shfl_xor_sync(0xffffffffu, v, 4);
        v += __shfl_xor_sync(0xffffffffu, v, 2);
        v += __shfl_xor_sync(0xffffffffu, v, 1);
        if ((l & 7) == 0) s_fp[g][row_local][half] = v;
    }

#pragma unroll
    for (int r = 0; r < 4; r++)
        *(float4*)&s_b[ty * 4 + r][c0] =
            make_float4(bacc[r][0], bacc[r][1], bacc[r][2], bacc[r][3]);
    __syncthreads();

#pragma unroll
    for (int r = 0; r < 4; r++) {
        float bf = s_b[0 * 4 + r][t] + s_b[1 * 4 + r][t]
                 + s_b[2 * 4 + r][t] + s_b[3 * 4 + r][t];
        g_bpart[(((long)b * 4 + q) * 4 + r) * 256 + t] = bf;
    }

    {
        int r = t >> 6, m = t & 63;
        g_fwd[((long)b * 4 + r) * 256 + q * 64 + m] = s_fp[r][m][0] + s_fp[r][m][1];
    }
}

// ---------------------------------------------------------------------------
// K4: read weights + read_words fused. Single-pass 4-way softmax reductions.
// ---------------------------------------------------------------------------
__global__ __launch_bounds__(256) void k_rw(float* __restrict__ out) {
    int b = blockIdx.x, t = threadIdx.x;
    int w = t >> 5, l = t & 31, li = l & 15, half = l >> 4;
    const float* P = g_P + (long)b * 512;

    __shared__ float s_rw[4][256];
    __shared__ __align__(16) float4 s_part[16][4][16];
    __shared__ float s_m32[32];
    __shared__ float s_s32[32];

    float mn2t = g_mn2[(long)b * 256 + t];
    float sim[4], fw[4], bfin[4];
#pragma unroll
    for (int r = 0; r < 4; r++) {
        bfin[r] = g_bpart[(((long)b * 4 + 0) * 4 + r) * 256 + t]
                + g_bpart[(((long)b * 4 + 1) * 4 + r) * 256 + t]
                + g_bpart[(((long)b * 4 + 2) * 4 + r) * 256 + t]
                + g_bpart[(((long)b * 4 + 3) * 4 + r) * 256 + t];
        fw[r] = g_fwd[((long)b * 4 + r) * 256 + t];
        float rsr = softplusf_(P[OFF_RS + r]);
        float knr = g_rkn[(long)b * 4 + r];
        sim[r] = g_rdot[((long)b * 4 + r) * 256 + t] / (knr * mn2t + EPSF) * rsr;
    }

    // fused 4-way block max
    float m4[4] = {sim[0], sim[1], sim[2], sim[3]};
#pragma unroll
    for (int o = 16; o > 0; o >>= 1)
#pragma unroll
        for (int r = 0; r < 4; r++)
            m4[r] = fmaxf(m4[r], __shfl_xor_sync(0xffffffffu, m4[r], o));
    if (l == 0)
#pragma unroll
        for (int r = 0; r < 4; r++) s_m32[w * 4 + r] = m4[r];
    __syncthreads();
    float mx[4];
#pragma unroll
    for (int r = 0; r < 4; r++) {
        float m = s_m32[r];
#pragma unroll
        for (int k = 1; k < 8; k++) m = fmaxf(m, s_m32[k * 4 + r]);
        mx[r] = m;
    }

    // fused 4-way block sum of exp
    float ev[4], e4[4];
#pragma unroll
    for (int r = 0; r < 4; r++) { ev[r] = expf(sim[r] - mx[r]); e4[r] = ev[r]; }
#pragma unroll
    for (int o = 16; o > 0; o >>= 1)
#pragma unroll
        for (int r = 0; r < 4; r++)
            e4[r] += __shfl_xor_sync(0xffffffffu, e4[r], o);
    if (l == 0)
#pragma unroll
        for (int r = 0; r < 4; r++) s_s32[w * 4 + r] = e4[r];
    __syncthreads();

#pragma unroll
    for (int r = 0; r < 4; r++) {
        float sm = 0.f;
#pragma unroll
        for (int k = 0; k < 8; k++) sm += s_s32[k * 4 + r];
        float contentv = ev[r] / sm;

        float x0 = P[OFF_RM + r * 3 + 0];
        float x1 = P[OFF_RM + r * 3 + 1];
        float x2 = P[OFF_RM + r * 3 + 2];
        float m3 = fmaxf(x0, fmaxf(x1, x2));
        float e0 = expf(x0 - m3), e1 = expf(x1 - m3), e2 = expf(x2 - m3);
        float inv = 1.f / (e0 + e1 + e2);
        float bm = e0 * inv, fm = e1 * inv, cm = e2 * inv;

        float rwv = cm * contentv + fm * fw[r] + bm * bfin[r];
        out[O_RWT + ((long)b * 4 + r) * 256 + t] = rwv;
        s_rw[r][t] = rwv;
    }
    __syncthreads();

    float4 acc[4];
#pragma unroll
    for (int r = 0; r < 4; r++) acc[r] = make_float4(0.f, 0.f, 0.f, 0.f);

    const float4* memv = (const float4*)(out + O_MEM) + (long)b * 4096;
#pragma unroll 4
    for (int i = 0; i < 16; i++) {
        int n = 2 * (w + 8 * i) + half;
        float4 mv = __ldcs(&memv[n * 16 + li]);
#pragma unroll
        for (int r = 0; r < 4; r++) {
            float wr = s_rw[r][n];
            acc[r].x = fmaf(wr, mv.x, acc[r].x);
            acc[r].y = fmaf(wr, mv.y, acc[r].y);
            acc[r].z = fmaf(wr, mv.z, acc[r].z);
            acc[r].w = fmaf(wr, mv.w, acc[r].w);
        }
    }
    int g = w * 2 + half;
#pragma unroll
    for (int r = 0; r < 4; r++) s_part[g][r][li] = acc[r];
    __syncthreads();

    if (t < 64) {
        int r = t >> 4, c = t & 15;
        float4 s = make_float4(0.f, 0.f, 0.f, 0.f);
#pragma unroll
        for (int gg = 0; gg < 16; gg++) {
            float4 p = s_part[gg][r][c];
            s.x += p.x; s.y += p.y; s.z += p.z; s.w += p.w;
        }
        *(float4*)&out[O_RW + (long)b * 256 + r * 64 + 4 * c] = s;
    }
}

// ---------------------------------------------------------------------------
extern "C" void kernel_launch(void* const* d_in, const int* in_sizes, int n_in,
                              void* d_out, int out_size) {
    const float* controller = (const float*)d_in[0];
    const float* memory     = (const float*)d_in[1];
    const float* prw        = (const float*)d_in[2];
    const float* pww        = (const float*)d_in[3];
    const float* pl         = (const float*)d_in[4];
    const float* pprec      = (const float*)d_in[5];
    const float* pu         = (const float*)d_in[6];

    WPtrs p;
    for (int i = 0; i < 10; i++) {
        p.W[i] = (const float*)d_in[7 + 2 * i];
        p.b[i] = (const float*)d_in[8 + 2 * i];
    }
    float* out = (float*)d_out;

    cudaFuncSetAttribute(k_head, cudaFuncAttributeMaxDynamicSharedMemorySize, 65536);

    k_pack<<<2048, 256>>>(p);
    k_gemm<<<dim3(8, 16), 256>>>(controller);
    k_head<<<1024, 256, 65536>>>(memory, prw, pww, pprec, pu, out);
    k_link_gen<<<dim3(1024, 4), 256>>>(pl, pprec, prw, out);
    k_rw<<<1024, 256>>>(out);
}

// round 12
// speedup vs baseline: 1.1039x; 1.0203x over previous
#include <cuda_runtime.h>
#include <math.h>

#define DEV_INLINE __device__ __forceinline__

constexpr float EPSF = 1e-6f;

// packed projection column offsets
constexpr int OFF_WV = 0;
constexpr int OFF_EV = 64;
constexpr int OFF_FG = 128;
constexpr int OFF_AG = 132;
constexpr int OFF_WG = 133;
constexpr int OFF_RM = 134;
constexpr int OFF_WS = 146;
constexpr int OFF_RS = 147;
constexpr int OFF_WK = 151;
constexpr int OFF_RK = 215;

// output offsets (floats): read_words, memory, read_weights, write_weights,
// link, precedence, usage
constexpr long O_RW    = 0L;
constexpr long O_MEM   = 262144L;
constexpr long O_RWT   = 17039360L;
constexpr long O_WW    = 18087936L;
constexpr long O_LINK  = 18350080L;
constexpr long O_PREC  = 85458944L;
constexpr long O_USAGE = 85721088L;

__device__ float g_WP[1024 * 512];
__device__ float g_bias[512];
__device__ float g_P[1024 * 512];
__device__ float g_ww[1024 * 256];
__device__ float g_mn2[1024 * 256];
__device__ float g_rdot[1024 * 4 * 256];
__device__ float g_rkn[1024 * 4];
__device__ float g_fwd[1024 * 4 * 256];          // forward weights [b][r][n]
__device__ float g_bpart[1024 * 4 * 4 * 256];    // backward partials [b][q][r][n]

__constant__ int c_start[11] = {0, 64, 128, 132, 133, 134, 146, 147, 151, 215, 471};

struct WPtrs { const float* W[10]; const float* b[10]; };

DEV_INLINE float sigmoidf_(float x) { return 1.0f / (1.0f + expf(-x)); }
DEV_INLINE float softplusf_(float x) { return x > 20.0f ? x : log1pf(expf(x)); }

DEV_INLINE float warpSum(float v) {
#pragma unroll
    for (int o = 16; o > 0; o >>= 1) v += __shfl_xor_sync(0xffffffffu, v, o);
    return v;
}

DEV_INLINE float halfSum(float v) {
#pragma unroll
    for (int o = 8; o > 0; o >>= 1) v += __shfl_xor_sync(0xffffffffu, v, o);
    return v;
}

DEV_INLINE float blockSumFast(float v, float* s8) {
    __syncthreads();
    v = warpSum(v);
    if ((threadIdx.x & 31) == 0) s8[threadIdx.x >> 5] = v;
    __syncthreads();
    float r = 0.f;
#pragma unroll
    for (int k = 0; k < 8; k++) r += s8[k];
    return r;
}

DEV_INLINE float blockMaxFast(float v, float* s8) {
    __syncthreads();
#pragma unroll
    for (int o = 16; o > 0; o >>= 1) v = fmaxf(v, __shfl_xor_sync(0xffffffffu, v, o));
    if ((threadIdx.x & 31) == 0) s8[threadIdx.x >> 5] = v;
    __syncthreads();
    float r = s8[0];
#pragma unroll
    for (int k = 1; k < 8; k++) r = fmaxf(r, s8[k]);
    return r;
}

// packed f32x2 helpers (Blackwell)
#define PACK2(out, lo, hi) \
    asm("mov.b64 %0, {%1, %2};" : "=l"(out) : "f"(lo), "f"(hi))
#define UNPACK2(lo, hi, in) \
    asm("mov.b64 {%0, %1}, %2;" : "=f"(lo), "=f"(hi) : "l"(in))
#define MUL2(d, a, b) \
    asm("mul.rn.f32x2 %0, %1, %2;" : "=l"(d) : "l"(a), "l"(b))
#define ADD2(d, a, b) \
    asm("add.rn.f32x2 %0, %1, %2;" : "=l"(d) : "l"(a), "l"(b))
#define FMA2(d, a, b, c) \
    asm("fma.rn.f32x2 %0, %1, %2, %3;" : "=l"(d) : "l"(a), "l"(b), "l"(c))
#define FMA2ACC(d, a, b) \
    asm("fma.rn.f32x2 %0, %1, %2, %0;" : "+l"(d) : "l"(a), "l"(b))

// ---------------------------------------------------------------------------
// K0: pack 10 weight matrices into [1024][512] (cols >= 471 zero) + bias row
// ---------------------------------------------------------------------------
__global__ void k_pack(WPtrs p) {
    int idx = blockIdx.x * blockDim.x + threadIdx.x;
    int k = idx >> 9;
    int c = idx & 511;
    float v = 0.f, bv = 0.f;
    if (c < 471) {
        int s = 0;
#pragma unroll
        for (int i = 1; i < 10; i++) if (c >= c_start[i]) s = i;
        int lc = c - c_start[s];
        int od = c_start[s + 1] - c_start[s];
        v = p.W[s][k * od + lc];
        bv = p.b[s][lc];
    }
    g_WP[idx] = v;
    if (k == 0) g_bias[c] = bv;
}

// ---------------------------------------------------------------------------
// K1: P[1024][512] = controller @ WP + bias.  64x64 tile, BK=16, 256 thr.
//     Inner loop uses packed fma.rn.f32x2 (2 MACs/instr).
// ---------------------------------------------------------------------------
__global__ __launch_bounds__(256) void k_gemm(const float* __restrict__ A) {
    __shared__ __align__(16) float sA[16][64];
    __shared__ __align__(16) float sB[16][64];
    int t = threadIdx.x;
    int bx = blockIdx.x, by = blockIdx.y;
    int tx = t & 15, ty = t >> 4;
    int arow = t >> 2, ak = (t & 3) << 2;
    int brow = t >> 4, bcol = (t & 15) << 2;

    const float* aptr = A + (long)(by * 64 + arow) * 1024 + ak;
    const float* bptr = g_WP + (long)brow * 512 + bx * 64 + bcol;

    unsigned long long acc01[4], acc23[4];
#pragma unroll
    for (int i = 0; i < 4; i++) { acc01[i] = 0ull; acc23[i] = 0ull; }

    float4 av = *(const float4*)(aptr);
    float4 bv = *(const float4*)(bptr);

    for (int kk = 0; kk < 1024; kk += 16) {
        __syncthreads();
        sA[ak + 0][arow] = av.x;
        sA[ak + 1][arow] = av.y;
        sA[ak + 2][arow] = av.z;
        sA[ak + 3][arow] = av.w;
        *(float4*)&sB[brow][bcol] = bv;
        __syncthreads();
        if (kk + 16 < 1024) {
            av = *(const float4*)(aptr + kk + 16);
            bv = *(const float4*)(bptr + (long)(kk + 16) * 512);
        }
#pragma unroll
        for (int k = 0; k < 16; k++) {
            float4 a4 = *(const float4*)&sA[k][ty << 2];
            float4 b4 = *(const float4*)&sB[k][tx << 2];
            unsigned long long b01, b23;
            PACK2(b01, b4.x, b4.y);
            PACK2(b23, b4.z, b4.w);
            unsigned long long aa0, aa1, aa2, aa3;
            PACK2(aa0, a4.x, a4.x);
            PACK2(aa1, a4.y, a4.y);
            PACK2(aa2, a4.z, a4.z);
            PACK2(aa3, a4.w, a4.w);
            FMA2ACC(acc01[0], aa0, b01);
            FMA2ACC(acc23[0], aa0, b23);
            FMA2ACC(acc01[1], aa1, b01);
            FMA2ACC(acc23[1], aa1, b23);
            FMA2ACC(acc01[2], aa2, b01);
            FMA2ACC(acc23[2], aa2, b23);
            FMA2ACC(acc01[3], aa3, b01);
            FMA2ACC(acc23[3], aa3, b23);
        }
    }

    int col0 = bx * 64 + (tx << 2);
    float b0 = g_bias[col0], b1 = g_bias[col0 + 1], b2 = g_bias[col0 + 2], b3 = g_bias[col0 + 3];
    float* pout = g_P + (long)(by * 64 + (ty << 2)) * 512 + col0;
#pragma unroll
    for (int i = 0; i < 4; i++) {
        float lo0, lo1, hi0, hi1;
        UNPACK2(lo0, lo1, acc01[i]);
        UNPACK2(hi0, hi1, acc23[i]);
        float4 o;
        o.x = lo0 + b0;
        o.y = lo1 + b1;
        o.z = hi0 + b2;
        o.w = hi1 + b3;
        *(float4*)(pout + (long)i * 512) = o;
    }
}

// ---------------------------------------------------------------------------
// K2: fused head kernel. One block per batch (256 threads).
//     cp.async prefetch of the memory tile overlapped with usage + sort.
// ---------------------------------------------------------------------------
__global__ __launch_bounds__(256) void k_head(
    const float* __restrict__ mem, const float* __restrict__ prw,
    const float* __restrict__ pww, const float* __restrict__ pprec,
    const float* __restrict__ pu, float* __restrict__ out)
{
    extern __shared__ float4 s_mem4[];     // [256 rows][16 float4] = 64 KB
    __shared__ float s_sim[256];
    __shared__ float s_key[256];
    __shared__ int   s_idx[256];
    __shared__ float s_cp[256];
    __shared__ float s_alloc[256];
    __shared__ float s_wwv[256];
    __shared__ float s_wk[64];
    __shared__ float s_r8[8];

    int b = blockIdx.x, t = threadIdx.x;
    int w = t >> 5, l = t & 31, li = l & 15, half = l >> 4;
    const float* P = g_P + (long)b * 512;

    // --- kick off async copy of the old memory tile (hidden behind sort) ---
    const float4* memb = (const float4*)(mem + (long)b * 16384);
    unsigned sbase = (unsigned)__cvta_generic_to_shared(s_mem4);
#pragma unroll
    for (int i = 0; i < 16; i++) {
        asm volatile("cp.async.cg.shared.global [%0], [%1], 16;"
                     :: "r"(sbase + (t + 256 * i) * 16), "l"(memb + t + 256 * i));
    }
    asm volatile("cp.async.commit_group;");

    if (t < 64) s_wk[t] = P[OFF_WK + t];

    // --- usage (independent of memory tile) ---
    float pu_t = pu[(long)b * 256 + t];
    float pww_t = pww[(long)b * 256 + t];
    float uaw = pu_t + (1.f - pu_t) * pww_t;
    float phi = 1.f;
#pragma unroll
    for (int r = 0; r < 4; r++) {
        float fg = sigmoidf_(P[OFF_FG + r]);
        phi *= 1.f - fg * prw[((long)b * 4 + r) * 256 + t];
    }
    float usage = uaw * phi;
    out[O_USAGE + (long)b * 256 + t] = usage;

    // --- allocation: hybrid bitonic sort (shfl j<32, SMEM j>=32) ---
    float u2 = EPSF + (1.f - EPSF) * usage;
    float non = 1.f - u2;
    float key = -non;
    int   idx = t;

    for (int k = 2; k <= 256; k <<= 1) {
        for (int j = k >> 1; j > 0; j >>= 1) {
            float kb; int ib;
            if (j >= 32) {
                __syncthreads();
                s_key[t] = key; s_idx[t] = idx;
                __syncthreads();
                kb = s_key[t ^ j]; ib = s_idx[t ^ j];
            } else {
                kb = __shfl_xor_sync(0xffffffffu, key, j);
                ib = __shfl_xor_sync(0xffffffffu, idx, j);
            }
            bool lower = ((t & j) == 0);
            float ak = lower ? key : kb, bk = lower ? kb : key;
            int   ai = lower ? idx : ib, bi = lower ? ib : idx;
            bool agtb = (ak > bk) || (ak == bk && ai > bi);
            bool up = ((t & k) == 0);
            if (agtb == up) { key = lower ? bk : ak; idx = lower ? bi : ai; }
            else            { key = lower ? ak : bk; idx = lower ? ai : bi; }
        }
    }

    float s_non_t = -key;
    float v = 1.f - s_non_t;
#pragma unroll
    for (int off = 1; off < 32; off <<= 1) {
        float pv = __shfl_up_sync(0xffffffffu, v, off);
        if (l >= off) v *= pv;
    }
    __syncthreads();
    if (l == 31) s_r8[w] = v;
    __syncthreads();
    float pref = 1.f;
#pragma unroll
    for (int k = 0; k < 8; k++) if (k < w) pref *= s_r8[k];
    float incl = v * pref;
    s_cp[t] = incl;
    __syncthreads();
    float excl = (t > 0) ? s_cp[t - 1] : 1.f;
    s_alloc[idx] = s_non_t * excl;

    // --- write key norm + strength ---
    float sq = (t < 64) ? s_wk[t] * s_wk[t] : 0.f;
    float kn = sqrtf(blockSumFast(sq, s_r8));
    float ws = softplusf_(P[OFF_WS]);

    // --- wait for the memory tile ---
    asm volatile("cp.async.wait_group 0;");
    __syncthreads();

    float wk0 = s_wk[4 * li + 0], wk1 = s_wk[4 * li + 1];
    float wk2 = s_wk[4 * li + 2], wk3 = s_wk[4 * li + 3];

    // cosine similarity (2 rows per warp per iteration, 16-lane reductions)
#pragma unroll 4
    for (int i = 0; i < 16; i++) {
        int n = 2 * (w + 8 * i) + half;
        float4 mv = s_mem4[n * 16 + li];
        float d = wk0 * mv.x + wk1 * mv.y + wk2 * mv.z + wk3 * mv.w;
        float q = mv.x * mv.x + mv.y * mv.y + mv.z * mv.z + mv.w * mv.w;
        d = halfSum(d);
        q = halfSum(q);
        if (li == 0) s_sim[n] = d / (kn * sqrtf(q) + EPSF) * ws;
    }
    __syncthreads();

    float sv = s_sim[t];
    float mx = blockMaxFast(sv, s_r8);
    float ev = expf(sv - mx);
    float ssum = blockSumFast(ev, s_r8);
    float content = ev / ssum;

    // --- write weights + precedence ---
    float ag = sigmoidf_(P[OFF_AG]);
    float wg = sigmoidf_(P[OFF_WG]);
    float wwv = wg * (ag * s_alloc[t] + (1.f - ag) * content);
    out[O_WW + (long)b * 256 + t] = wwv;
    g_ww[(long)b * 256 + t] = wwv;
    s_wwv[t] = wwv;
    float sww = blockSumFast(wwv, s_r8);
    out[O_PREC + (long)b * 256 + t] = (1.f - sww) * pprec[(long)b * 256 + t] + wwv;

    if (w < 4) {
        float a = P[OFF_RK + w * 64 + l];
        float c = P[OFF_RK + w * 64 + l + 32];
        float q2 = warpSum(a * a + c * c);
        if (l == 0) g_rkn[(long)b * 4 + w] = sqrtf(q2);
    }
    __syncthreads();

    // --- memory erase/write + rdot/mn2 ---
    float e0 = sigmoidf_(P[OFF_EV + 4 * li + 0]);
    float e1 = sigmoidf_(P[OFF_EV + 4 * li + 1]);
    float e2 = sigmoidf_(P[OFF_EV + 4 * li + 2]);
    float e3 = sigmoidf_(P[OFF_EV + 4 * li + 3]);
    float v0 = P[OFF_WV + 4 * li + 0];
    float v1 = P[OFF_WV + 4 * li + 1];
    float v2 = P[OFF_WV + 4 * li + 2];
    float v3 = P[OFF_WV + 4 * li + 3];
    float rk[4][4];
#pragma unroll
    for (int r = 0; r < 4; r++)
#pragma unroll
        for (int j = 0; j < 4; j++) rk[r][j] = P[OFF_RK + r * 64 + 4 * li + j];

    float4* outm = (float4*)(out + O_MEM) + (long)b * 4096;
#pragma unroll 2
    for (int i = 0; i < 16; i++) {
        int n = 2 * (w + 8 * i) + half;
        float4 mv = s_mem4[n * 16 + li];
        float wwn = s_wwv[n];
        float4 nv;
        nv.x = mv.x * (1.f - wwn * e0) + wwn * v0;
        nv.y = mv.y * (1.f - wwn * e1) + wwn * v1;
        nv.z = mv.z * (1.f - wwn * e2) + wwn * v2;
        nv.w = mv.w * (1.f - wwn * e3) + wwn * v3;
        outm[n * 16 + li] = nv;
        float q  = nv.x * nv.x + nv.y * nv.y + nv.z * nv.z + nv.w * nv.w;
        float d0 = rk[0][0] * nv.x + rk[0][1] * nv.y + rk[0][2] * nv.z + rk[0][3] * nv.w;
        float d1 = rk[1][0] * nv.x + rk[1][1] * nv.y + rk[1][2] * nv.z + rk[1][3] * nv.w;
        float d2 = rk[2][0] * nv.x + rk[2][1] * nv.y + rk[2][2] * nv.z + rk[2][3] * nv.w;
        float d3 = rk[3][0] * nv.x + rk[3][1] * nv.y + rk[3][2] * nv.z + rk[3][3] * nv.w;
        q = halfSum(q); d0 = halfSum(d0); d1 = halfSum(d1); d2 = halfSum(d2); d3 = halfSum(d3);
        if (li == 0) {
            g_mn2[(long)b * 256 + n] = sqrtf(q);
            g_rdot[((long)b * 4 + 0) * 256 + n] = d0;
            g_rdot[((long)b * 4 + 1) * 256 + n] = d1;
            g_rdot[((long)b * 4 + 2) * 256 + n] = d2;
            g_rdot[((long)b * 4 + 3) * 256 + n] = d3;
        }
    }
}

// ---------------------------------------------------------------------------
// K3: link generation, 4 blocks/batch (64 rows each). Prefetched loads +
//     streaming hints. Packed f32x2 gen + backward; inline forward reduce.
// ---------------------------------------------------------------------------
__global__ __launch_bounds__(256, 4) void k_link_gen(
    const float* __restrict__ pl, const float* __restrict__ pprec,
    const float* __restrict__ prw, float* __restrict__ out)
{
    int b = blockIdx.x, q = blockIdx.y, t = threadIdx.x;
    int l = t & 31;
    int ty = t >> 6, tx = t & 63;
    int half = (t >> 5) & 1;

    __shared__ float s_ww[256], s_pp[256];
    __shared__ float s_prw[4][256];
    __shared__ unsigned long long s_prw2[4][256];   // duplicated-lane packed prw
    __shared__ float s_fp[4][64][2];
    __shared__ __align__(16) float s_b[16][256];

    s_ww[t] = g_ww[(long)b * 256 + t];
    s_pp[t] = pprec[(long)b * 256 + t];
#pragma unroll
    for (int r = 0; r < 4; r++) {
        float pv_ = prw[((long)b * 4 + r) * 256 + t];
        s_prw[r][t] = pv_;
        unsigned long long d2;
        PACK2(d2, pv_, pv_);
        s_prw2[r][t] = d2;
    }
    __syncthreads();

    int c0 = tx * 4;
    unsigned long long negwwc01, negwwc23, ppc01, ppc23;
    PACK2(negwwc01, -s_ww[c0 + 0], -s_ww[c0 + 1]);
    PACK2(negwwc23, -s_ww[c0 + 2], -s_ww[c0 + 3]);
    PACK2(ppc01, s_pp[c0 + 0], s_pp[c0 + 1]);
    PACK2(ppc23, s_pp[c0 + 2], s_pp[c0 + 3]);
    unsigned long long pr01[4], pr23[4];
#pragma unroll
    for (int r = 0; r < 4; r++) {
        PACK2(pr01[r], s_prw[r][c0 + 0], s_prw[r][c0 + 1]);
        PACK2(pr23[r], s_prw[r][c0 + 2], s_prw[r][c0 + 3]);
    }

    unsigned long long bacc01[4], bacc23[4];
#pragma unroll
    for (int r = 0; r < 4; r++) { bacc01[r] = 0ull; bacc23[r] = 0ull; }

    const float4* plb = (const float4*)(pl + (long)b * 65536);
    float4* lout = (float4*)(out + O_LINK) + (long)b * 16384;

    int base0 = q * 64;
    int m_cur = base0 + ty;
    float4 pv = __ldcs(&plb[m_cur * 64 + tx]);

#pragma unroll
    for (int i = 0; i < 16; i++) {
        int m = base0 + ((i >> 3) << 5) + ty + ((i & 7) << 2);
        int row_local = m - base0;
        float4 cur = pv;
        if (i < 15) {
            int i2 = i + 1;
            int mn = base0 + ((i2 >> 3) << 5) + ty + ((i2 & 7) << 2);
            pv = __ldcs(&plb[mn * 64 + tx]);
        }

        unsigned long long cur01, cur23;
        PACK2(cur01, cur.x, cur.y);
        PACK2(cur23, cur.z, cur.w);

        float wwm = s_ww[m];
        float t1 = 1.f - wwm;
        unsigned long long t12, wwm2;
        PACK2(t12, t1, t1);
        PACK2(wwm2, wwm, wwm);

        unsigned long long coef01, coef23, base01, base23, Lv01, Lv23;
        ADD2(coef01, t12, negwwc01);
        ADD2(coef23, t12, negwwc23);
        MUL2(base01, wwm2, ppc01);
        MUL2(base23, wwm2, ppc23);
        FMA2(Lv01, coef01, cur01, base01);
        FMA2(Lv23, coef23, cur23, base23);

        // diagonal zero (rare, predicated)
        if (tx == (m >> 2)) {
            int j = m & 3;
            if (j == 0)      Lv01 &= 0xFFFFFFFF00000000ull;
            else if (j == 1) Lv01 &= 0x00000000FFFFFFFFull;
            else if (j == 2) Lv23 &= 0xFFFFFFFF00000000ull;
            else             Lv23 &= 0x00000000FFFFFFFFull;
        }

        float o0, o1, o2, o3;
        UNPACK2(o0, o1, Lv01);
        UNPACK2(o2, o3, Lv23);
        __stcs(&lout[m * 64 + tx], make_float4(o0, o1, o2, o3));

        // backward accumulation: packed, duplicated-lane prw from SMEM
#pragma unroll
        for (int r = 0; r < 4; r++) {
            unsigned long long wpm2 = s_prw2[r][m];
            FMA2ACC(bacc01[r], wpm2, Lv01);
            FMA2ACC(bacc23[r], wpm2, Lv23);
        }

        // forward partial: packed dot of 4, then lane combine
        float fp[4];
#pragma unroll
        for (int r = 0; r < 4; r++) {
            unsigned long long f2;
            MUL2(f2, Lv01, pr01[r]);
            FMA2(f2, Lv23, pr23[r], f2);
            float fa, fb;
            UNPACK2(fa, fb, f2);
            fp[r] = fa + fb;
        }

#pragma unroll
        for (int r = 0; r < 4; r++) {
            fp[r] += __shfl_xor_sync(0xffffffffu, fp[r], 16);
            fp[r] += __shfl_xor_sync(0xffffffffu, fp[r], 8);
        }
        int g = l >> 3;
        float v = (g == 0) ? fp[0] : (g == 1) ? fp[1] : (g == 2) ? fp[2] : fp[3];
        v += __shfl_xor_sync(0xffffffffu, v, 4);
        v += __shfl_xor_sync(0xffffffffu, v, 2);
        v += __shfl_xor_sync(0xffffffffu, v, 1);
        if ((l & 7) == 0) s_fp[g][row_local][half] = v;
    }

#pragma unroll
    for (int r = 0; r < 4; r++) {
        float b0, b1, b2, b3;
        UNPACK2(b0, b1, bacc01[r]);
        UNPACK2(b2, b3, bacc23[r]);
        *(float4*)&s_b[ty * 4 + r][c0] = make_float4(b0, b1, b2, b3);
    }
    __syncthreads();

#pragma unroll
    for (int r = 0; r < 4; r++) {
        float bf = s_b[0 * 4 + r][t] + s_b[1 * 4 + r][t]
                 + s_b[2 * 4 + r][t] + s_b[3 * 4 + r][t];
        g_bpart[(((long)b * 4 + q) * 4 + r) * 256 + t] = bf;
    }

    {
        int r = t >> 6, m = t & 63;
        g_fwd[((long)b * 4 + r) * 256 + q * 64 + m] = s_fp[r][m][0] + s_fp[r][m][1];
    }
}

// ---------------------------------------------------------------------------
// K4: read weights + read_words fused. Single-pass 4-way softmax reductions.
// ---------------------------------------------------------------------------
__global__ __launch_bounds__(256) void k_rw(float* __restrict__ out) {
    int b = blockIdx.x, t = threadIdx.x;
    int w = t >> 5, l = t & 31, li = l & 15, half = l >> 4;
    const float* P = g_P + (long)b * 512;

    __shared__ float s_rw[4][256];
    __shared__ __align__(16) float4 s_part[16][4][16];
    __shared__ float s_m32[32];
    __shared__ float s_s32[32];

    float mn2t = g_mn2[(long)b * 256 + t];
    float sim[4], fw[4], bfin[4];
#pragma unroll
    for (int r = 0; r < 4; r++) {
        bfin[r] = g_bpart[(((long)b * 4 + 0) * 4 + r) * 256 + t]
                + g_bpart[(((long)b * 4 + 1) * 4 + r) * 256 + t]
                + g_bpart[(((long)b * 4 + 2) * 4 + r) * 256 + t]
                + g_bpart[(((long)b * 4 + 3) * 4 + r) * 256 + t];
        fw[r] = g_fwd[((long)b * 4 + r) * 256 + t];
        float rsr = softplusf_(P[OFF_RS + r]);
        float knr = g_rkn[(long)b * 4 + r];
        sim[r] = g_rdot[((long)b * 4 + r) * 256 + t] / (knr * mn2t + EPSF) * rsr;
    }

    // fused 4-way block max
    float m4[4] = {sim[0], sim[1], sim[2], sim[3]};
#pragma unroll
    for (int o = 16; o > 0; o >>= 1)
#pragma unroll
        for (int r = 0; r < 4; r++)
            m4[r] = fmaxf(m4[r], __shfl_xor_sync(0xffffffffu, m4[r], o));
    if (l == 0)
#pragma unroll
        for (int r = 0; r < 4; r++) s_m32[w * 4 + r] = m4[r];
    __syncthreads();
    float mx[4];
#pragma unroll
    for (int r = 0; r < 4; r++) {
        float m = s_m32[r];
#pragma unroll
        for (int k = 1; k < 8; k++) m = fmaxf(m, s_m32[k * 4 + r]);
        mx[r] = m;
    }

    // fused 4-way block sum of exp
    float ev[4], e4[4];
#pragma unroll
    for (int r = 0; r < 4; r++) { ev[r] = expf(sim[r] - mx[r]); e4[r] = ev[r]; }
#pragma unroll
    for (int o = 16; o > 0; o >>= 1)
#pragma unroll
        for (int r = 0; r < 4; r++)
            e4[r] += __shfl_xor_sync(0xffffffffu, e4[r], o);
    if (l == 0)
#pragma unroll
        for (int r = 0; r < 4; r++) s_s32[w * 4 + r] = e4[r];
    __syncthreads();

#pragma unroll
    for (int r = 0; r < 4; r++) {
        float sm = 0.f;
#pragma unroll
        for (int k = 0; k < 8; k++) sm += s_s32[k * 4 + r];
        float contentv = ev[r] / sm;

        float x0 = P[OFF_RM + r * 3 + 0];
        float x1 = P[OFF_RM + r * 3 + 1];
        float x2 = P[OFF_RM + r * 3 + 2];
        float m3 = fmaxf(x0, fmaxf(x1, x2));
        float e0 = expf(x0 - m3), e1 = expf(x1 - m3), e2 = expf(x2 - m3);
        float inv = 1.f / (e0 + e1 + e2);
        float bm = e0 * inv, fm = e1 * inv, cm = e2 * inv;

        float rwv = cm * contentv + fm * fw[r] + bm * bfin[r];
        out[O_RWT + ((long)b * 4 + r) * 256 + t] = rwv;
        s_rw[r][t] = rwv;
    }
    __syncthreads();

    float4 acc[4];
#pragma unroll
    for (int r = 0; r < 4; r++) acc[r] = make_float4(0.f, 0.f, 0.f, 0.f);

    const float4* memv = (const float4*)(out + O_MEM) + (long)b * 4096;
#pragma unroll 4
    for (int i = 0; i < 16; i++) {
        int n = 2 * (w + 8 * i) + half;
        float4 mv = __ldcs(&memv[n * 16 + li]);
#pragma unroll
        for (int r = 0; r < 4; r++) {
            float wr = s_rw[r][n];
            acc[r].x = fmaf(wr, mv.x, acc[r].x);
            acc[r].y = fmaf(wr, mv.y, acc[r].y);
            acc[r].z = fmaf(wr, mv.z, acc[r].z);
            acc[r].w = fmaf(wr, mv.w, acc[r].w);
        }
    }
    int g = w * 2 + half;
#pragma unroll
    for (int r = 0; r < 4; r++) s_part[g][r][li] = acc[r];
    __syncthreads();

    if (t < 64) {
        int r = t >> 4, c = t & 15;
        float4 s = make_float4(0.f, 0.f, 0.f, 0.f);
#pragma unroll
        for (int gg = 0; gg < 16; gg++) {
            float4 p = s_part[gg][r][c];
            s.x += p.x; s.y += p.y; s.z += p.z; s.w += p.w;
        }
        *(float4*)&out[O_RW + (long)b * 256 + r * 64 + 4 * c] = s;
    }
}

// ---------------------------------------------------------------------------
extern "C" void kernel_launch(void* const* d_in, const int* in_sizes, int n_in,
                              void* d_out, int out_size) {
    const float* controller = (const float*)d_in[0];
    const float* memory     = (const float*)d_in[1];
    const float* prw        = (const float*)d_in[2];
    const float* pww        = (const float*)d_in[3];
    const float* pl         = (const float*)d_in[4];
    const float* pprec      = (const float*)d_in[5];
    const float* pu         = (const float*)d_in[6];

    WPtrs p;
    for (int i = 0; i < 10; i++) {
        p.W[i] = (const float*)d_in[7 + 2 * i];
        p.b[i] = (const float*)d_in[8 + 2 * i];
    }
    float* out = (float*)d_out;

    cudaFuncSetAttribute(k_head, cudaFuncAttributeMaxDynamicSharedMemorySize, 65536);

    k_pack<<<2048, 256>>>(p);
    k_gemm<<<dim3(8, 16), 256>>>(controller);
    k_head<<<1024, 256, 65536>>>(memory, prw, pww, pprec, pu, out);
    k_link_gen<<<dim3(1024, 4), 256>>>(pl, pprec, prw, out);
    k_rw<<<1024, 256>>>(out);
}